// round 14
// baseline (speedup 1.0000x reference)
#include <cuda_runtime.h>
#include <cuda_bf16.h>
#include <mma.h>
#include <cstdint>

using namespace nvcuda;

#define Bsz   2
#define Cdim  192
#define Hdim  256
#define Wdim  256
#define HW    65536
#define CHW   12582912
#define NHEAD 6
#define HD    32
#define NTOK  131072
#define C3    576
#define HID   384
#define NWIN  2048

// ---------------- scratch (device globals; no allocation allowed) ----------------
__device__ __nv_bfloat16 g_roll[(size_t)Bsz*CHW];
__device__ __nv_bfloat16 g_win[(size_t)NTOK*Cdim];
__device__ __nv_bfloat16 g_qkv[(size_t)NTOK*C3];
__device__ __nv_bfloat16 g_attnout[(size_t)NTOK*Cdim];
__device__ __nv_bfloat16 g_yattn[(size_t)Bsz*CHW];
__device__ float         g_gappart[(size_t)Bsz*Cdim*256];
__device__ float         g_s[Bsz*Cdim];
__device__ __nv_bfloat16 g_t[(size_t)NTOK*Cdim];
__device__ __nv_bfloat16 g_h[(size_t)NTOK*HID];
__device__ __nv_bfloat16 g_wqkv[Cdim*C3];
__device__ float         g_bqkv[C3];
__device__ __nv_bfloat16 g_wproj[Cdim*Cdim];
__device__ __nv_bfloat16 g_wfc1[Cdim*HID];
__device__ __nv_bfloat16 g_wfc2[HID*Cdim];

// ---------------- all weight conversions in one kernel (scale folded into q cols) -------------
__global__ void k_conv_all(const float* __restrict__ qw, const float* __restrict__ qb,
                           const float* __restrict__ pw, const float* __restrict__ f1,
                           const float* __restrict__ f2){
    int i = blockIdx.x*256 + threadIdx.x;
    const float sc = 0.17677669529663687f; // 32^-0.5
    if (i < Cdim*C3){
        int o = i % C3;
        float f = qw[i];
        if (o < Cdim) f *= sc;
        g_wqkv[i] = __float2bfloat16(f);
    }
    if (i < C3){
        float f = qb[i];
        if (i < Cdim) f *= sc;
        g_bqkv[i] = f;
    }
    if (i < Cdim*Cdim) g_wproj[i] = __float2bfloat16(pw[i]);
    if (i < Cdim*HID)  g_wfc1[i]  = __float2bfloat16(f1[i]);
    if (i < HID*Cdim)  g_wfc2[i]  = __float2bfloat16(f2[i]);
}

// ---------------- norm1 (over C per pixel) fused with the "buggy" flat roll ----------------
__global__ void k_norm1_roll(const float* __restrict__ x,
                             const float* __restrict__ nw, const float* __restrict__ nb){
    __shared__ float tile[Cdim][33];
    __shared__ float red1[8][32], red2[8][32];
    __shared__ float s_mu[32], s_ri[32];
    __shared__ float s_w[Cdim], s_b[Cdim];
    int b = blockIdx.y;
    int p0 = blockIdx.x * 32;
    const float* xb = x + (size_t)b*CHW;
    int tid = threadIdx.x;
    if (tid < Cdim){ s_w[tid]=nw[tid]; s_b[tid]=nb[tid]; }
    #pragma unroll
    for (int it=0; it<24; it++){
        int idx = it*256+tid;
        int c = idx>>5, p = idx&31;
        tile[c][p] = xb[(size_t)c*HW + p0 + p];
    }
    __syncthreads();
    int p = tid&31, g = tid>>5;
    float sum=0.f, sq=0.f;
    for (int c=g; c<Cdim; c+=8){ float v=tile[c][p]; sum+=v; sq+=v*v; }
    red1[g][p]=sum; red2[g][p]=sq;
    __syncthreads();
    if (g==0){
        float s=0.f,q=0.f;
        #pragma unroll
        for (int k=0;k<8;k++){ s+=red1[k][p]; q+=red2[k][p]; }
        float mu = s*(1.f/Cdim);
        float var = q*(1.f/Cdim) - mu*mu;
        s_mu[p]=mu; s_ri[p]=rsqrtf(var+1e-6f);
    }
    __syncthreads();
    __nv_bfloat16* rb = g_roll + (size_t)b*CHW;
    #pragma unroll
    for (int it=0; it<24; it++){
        int idx = it*256+tid;
        int c = idx>>5, pp = idx&31;
        float v = (tile[c][pp]-s_mu[pp])*s_ri[pp]*s_w[c]+s_b[c];
        int f = c*HW + p0 + pp;
        int i = f/49152; int r = f - i*49152; int j = r/192; int k = r - j*192;
        int t = ((i-4)&255)*49152 + ((j-4)&255)*192 + k;
        rb[t] = __float2bfloat16(v);
    }
}

// ---------------- window partition: rolled BCHW -> (win, n, c) tokens ----------------
__global__ void k_win_gather(){
    __shared__ __nv_bfloat16 s[96][66];
    int wi = blockIdx.x; int tid = threadIdx.x;
    int b = wi>>10, gh=(wi&1023)>>5, gw=wi&31;
    const __nv_bfloat16* rb = g_roll + (size_t)b*CHW;
    size_t base = (size_t)(gh*8)*256 + gw*8;
    for (int chunk=0; chunk<2; chunk++){
        int c0 = chunk*96;
        #pragma unroll
        for (int it=0; it<24; it++){
            int idx = it*256+tid;
            int cl = idx>>6, n = idx&63;
            s[cl][n] = rb[(size_t)(c0+cl)*HW + base + (n>>3)*256 + (n&7)];
        }
        __syncthreads();
        #pragma unroll
        for (int it=0; it<24; it++){
            int idx = it*256+tid;
            int n = idx/96, cl = idx%96;
            g_win[((size_t)wi*64+n)*Cdim + c0 + cl] = s[cl][n];
        }
        __syncthreads();
    }
}

// ---------------- GEMM mainloop: 256x64 CTA tile, 8 warps x (64x32), ldm=72 ------------------
// K processed in 192-wide segments: B segment resident, A double-buffered in 64-chunks.
// Returns smem Cs[256][68] (raw accum, pre-bias), after syncthreads.
template<int K, int N>
__device__ __forceinline__ float* gemm_main(const __nv_bfloat16* __restrict__ A,
                                            const __nv_bfloat16* __restrict__ Bm){
    extern __shared__ __align__(16) char sm[];
    __nv_bfloat16* Bs = (__nv_bfloat16*)sm;                       // [192][72]
    __nv_bfloat16* As = (__nv_bfloat16*)(sm + 192*72*2);          // [2][256][72]
    float*         Cs = (float*)(sm + 192*72*2);                  // [256][68] (aliases As)
    const int tid = threadIdx.x;
    const int m0 = blockIdx.x*256, n0 = blockIdx.y*64;
    const int warp = tid>>5, wr = warp>>1, wc = warp&1;

    auto loadB = [&](int s){
        #pragma unroll
        for (int it=0; it<6; it++){
            int idx = it*256+tid;
            int row = idx>>3, u = idx&7;
            *(uint4*)&Bs[row*72 + u*8] = *(const uint4*)&Bm[(size_t)(s*192+row)*N + n0 + u*8];
        }
    };
    auto loadA = [&](int s, int c, int buf){
        #pragma unroll
        for (int it=0; it<8; it++){
            int idx = it*256+tid;
            int row = idx>>3, u = idx&7;
            *(uint4*)&As[(size_t)(buf*256+row)*72 + u*8] =
                *(const uint4*)&A[(size_t)(m0+row)*K + s*192 + c*64 + u*8];
        }
    };

    wmma::fragment<wmma::accumulator,16,16,16,float> acc[4][2];
    #pragma unroll
    for (int i=0;i<4;i++)
        #pragma unroll
        for (int j=0;j<2;j++) wmma::fill_fragment(acc[i][j], 0.f);

    constexpr int NS = K/192;
    #pragma unroll
    for (int s=0;s<NS;s++){
        loadB(s);
        loadA(s,0,0);
        __syncthreads();
        #pragma unroll
        for (int c=0;c<3;c++){
            if (c<2) loadA(s,c+1,(c+1)&1);
            int buf = c&1;
            #pragma unroll
            for (int kk=0;kk<64;kk+=16){
                wmma::fragment<wmma::matrix_a,16,16,16,__nv_bfloat16,wmma::row_major> af[4];
                wmma::fragment<wmma::matrix_b,16,16,16,__nv_bfloat16,wmma::row_major> bf[2];
                #pragma unroll
                for (int i=0;i<4;i++)
                    wmma::load_matrix_sync(af[i], &As[(size_t)(buf*256+wr*64+i*16)*72 + kk], 72);
                #pragma unroll
                for (int j=0;j<2;j++)
                    wmma::load_matrix_sync(bf[j], &Bs[(size_t)(c*64+kk)*72 + wc*32+j*16], 72);
                #pragma unroll
                for (int i=0;i<4;i++)
                    #pragma unroll
                    for (int j=0;j<2;j++)
                        wmma::mma_sync(acc[i][j], af[i], bf[j], acc[i][j]);
            }
            __syncthreads();
        }
    }
    #pragma unroll
    for (int i=0;i<4;i++)
        #pragma unroll
        for (int j=0;j<2;j++)
            wmma::store_matrix_sync(&Cs[(size_t)(wr*64+i*16)*68 + wc*32+j*16], acc[i][j], 68, wmma::mem_row_major);
    __syncthreads();
    return Cs;
}

// qkv: plain bf16 epilogue
__global__ void __launch_bounds__(256,2) k_gemm_qkv(){
    float* Cs = gemm_main<Cdim,C3>(g_win, g_wqkv);
    const int tid = threadIdx.x;
    const int m0 = blockIdx.x*256, n0 = blockIdx.y*64;
    #pragma unroll
    for (int it=0; it<64; it++){
        int idx = it*256+tid;
        int r = idx>>6, cc = idx&63;
        float v = Cs[(size_t)r*68+cc] + g_bqkv[n0+cc];
        g_qkv[(size_t)(m0+r)*C3 + n0 + cc] = __float2bfloat16(v);
    }
}

// fc1: gelu epilogue
__global__ void __launch_bounds__(256,2) k_gemm_fc1(const float* __restrict__ bias){
    float* Cs = gemm_main<Cdim,HID>(g_t, g_wfc1);
    const int tid = threadIdx.x;
    const int m0 = blockIdx.x*256, n0 = blockIdx.y*64;
    #pragma unroll
    for (int it=0; it<64; it++){
        int idx = it*256+tid;
        int r = idx>>6, cc = idx&63;
        float v = Cs[(size_t)r*68+cc] + bias[n0+cc];
        v = 0.5f*v*(1.f+erff(v*0.70710678118654752f));
        g_h[(size_t)(m0+r)*HID + n0 + cc] = __float2bfloat16(v);
    }
}

// proj: fused window-reverse scatter into BCHW yattn + deterministic gap partials
__global__ void __launch_bounds__(256,2) k_gemm_proj_f(const float* __restrict__ bias){
    float* Cs = gemm_main<Cdim,Cdim>(g_attnout, g_wproj);
    __shared__ float sgap[4][64];
    const int tid = threadIdx.x;
    const int m0 = blockIdx.x*256, n0 = blockIdx.y*64;
    const int w0 = m0/64;                 // first of 4 windows (same batch, no straddle)
    const int b  = w0>>10;
    // scatter: token (wi, n) -> pixel b,c,(gh*8+(n>>3))*256 + gw*8+(n&7)
    const int w = (tid>>3)&3, q = tid&7, grp32 = tid>>5;
    {
        int wi = w0 + w;
        int gh = (wi&1023)>>5, gw = wi&31;
        size_t pixbase = (size_t)b*CHW + (size_t)gh*2048 + gw*8 + q;
        #pragma unroll
        for (int it=0; it<64; it++){
            int combo = it*8 + grp32;       // 0..511 = cc*8 + i
            int cc = combo>>3, i = combo&7;
            int r = w*64 + i*8 + q;
            float v = Cs[(size_t)r*68+cc] + bias[n0+cc];
            g_yattn[pixbase + (size_t)(n0+cc)*HW + i*256] = __float2bfloat16(v);
        }
    }
    // gap partials (sum of bf16-rounded outputs per channel over this tile's 256 tokens)
    {
        int cc = tid&63, grp = tid>>6;
        float s = 0.f;
        float bb = bias[n0+cc];
        #pragma unroll
        for (int k=0;k<64;k++){
            int r = grp*64+k;
            s += __bfloat162float(__float2bfloat16(Cs[(size_t)r*68+cc] + bb));
        }
        sgap[grp][cc] = s;
        __syncthreads();
        if (tid < 64){
            float t = sgap[0][tid]+sgap[1][tid]+sgap[2][tid]+sgap[3][tid];
            g_gappart[(size_t)(b*Cdim + n0 + tid)*256 + (blockIdx.x & 255)] = t;
        }
    }
}

// fc2: fused final residual  out = x + yattn*s + fc2(h)
__global__ void __launch_bounds__(256,2) k_gemm_fc2_f(const float* __restrict__ bias,
                                                      const float* __restrict__ x,
                                                      float* __restrict__ out){
    float* Cs = gemm_main<HID,Cdim>(g_h, g_wfc2);
    __shared__ float s_sc[64];
    const int tid = threadIdx.x;
    const int m0 = blockIdx.x*256, n0 = blockIdx.y*64;
    const int b = m0>>16, p0 = m0&65535;
    if (tid < 64) s_sc[tid] = g_s[b*Cdim + n0 + tid];
    __syncthreads();
    #pragma unroll
    for (int it=0; it<64; it++){
        int idx = it*256+tid;
        int cc = idx>>8, pp = idx&255;
        float v = Cs[(size_t)pp*68+cc] + bias[n0+cc];
        size_t off = (size_t)b*CHW + (size_t)(n0+cc)*HW + p0 + pp;
        float y = __bfloat162float(g_yattn[off]);
        out[off] = x[off] + y*s_sc[cc] + v;
    }
}

// ---------------- fused window attention, WMMA: 2 blocks/SM (112.5KB smem) ----------------
#define LDQ 584
#define ATT_SS  74752
#define ATT_RPB 109568
#define ATT_CLS 112272
#define ATT_SM  112528
__global__ void __launch_bounds__(256) k_attn(const float* __restrict__ rpb){
    extern __shared__ __align__(16) char sm[];
    __nv_bfloat16* sQ   = (__nv_bfloat16*)sm;                   // [64][584]
    float*         sS   = (float*)(sm + ATT_SS);                // [8][16*68]  (P aliases this)
    __nv_bfloat16* sRpb = (__nv_bfloat16*)(sm + ATT_RPB);       // [6*225]
    int*           sCls = (int*)(sm + ATT_CLS);                 // [64]
    int wi = blockIdx.x;
    int tid = threadIdx.x, warp = tid>>5, lane = tid&31;
    int gh = (wi & 1023) >> 5, gw = wi & 31;

    const __nv_bfloat16* qkvb = g_qkv + (size_t)wi*64*C3;
    #pragma unroll
    for (int it=0; it<18; it++){
        int idx = it*256+tid;
        int row = idx/72, u = idx%72;
        *(uint4*)&sQ[row*LDQ + u*8] = *(const uint4*)&qkvb[(size_t)row*C3 + u*8];
    }
    for (int i=tid; i<NHEAD*225; i+=256){
        int h = i/225, p = i%225;
        sRpb[h*225+p] = __float2bfloat16(rpb[p*NHEAD + h]);
    }
    if (tid < 64){
        int i = tid>>3, j = tid&7;
        int hg = gh*8+i, wg = gw*8+j;
        int rh = hg < 248 ? 0 : (hg < 252 ? 1 : 2);
        int rw = wg < 248 ? 0 : (wg < 252 ? 1 : 2);
        sCls[tid] = rh*3+rw;
    }
    __syncthreads();

    #pragma unroll
    for (int r=0; r<3; r++){
        int task = warp + 8*r;            // 0..23
        int h = task>>2, strip = task&3, n0 = strip*16;
        float*         Sw = sS + warp*16*68;
        __nv_bfloat16* Pw = (__nv_bfloat16*)Sw;     // alias: reads complete before writes
        // ---- S = Q Kt (16x64) ----
        wmma::fragment<wmma::accumulator,16,16,16,float> acc[4];
        #pragma unroll
        for (int j=0;j<4;j++) wmma::fill_fragment(acc[j], 0.f);
        #pragma unroll
        for (int kk=0; kk<32; kk+=16){
            wmma::fragment<wmma::matrix_a,16,16,16,__nv_bfloat16,wmma::row_major> aq;
            wmma::load_matrix_sync(aq, &sQ[(size_t)n0*LDQ + h*HD + kk], LDQ);
            #pragma unroll
            for (int j=0;j<4;j++){
                wmma::fragment<wmma::matrix_b,16,16,16,__nv_bfloat16,wmma::col_major> bk;
                wmma::load_matrix_sync(bk, &sQ[(size_t)(j*16)*LDQ + Cdim + h*HD + kk], LDQ);
                wmma::mma_sync(acc[j], aq, bk, acc[j]);
            }
        }
        #pragma unroll
        for (int j=0;j<4;j++)
            wmma::store_matrix_sync(&Sw[j*16], acc[j], 68, wmma::mem_row_major);
        __syncwarp();
        // ---- softmax with rpb bias + shift mask (lane: one row half) ----
        {
            int row = lane>>1, half = (lane&1)*32;
            int n = n0+row, ni = n>>3, nj = n&7;
            int cn = sCls[n];
            const __nv_bfloat16* rh = sRpb + h*225;
            float e[32]; float mx = -1e30f;
            #pragma unroll
            for (int c=0;c<32;c++){
                int m = half+c;
                float v = Sw[row*68+m] + __bfloat162float(rh[(ni-(m>>3)+7)*15 + (nj-(m&7)+7)]);
                if (cn != sCls[m]) v -= 100.f;
                e[c]=v; mx = fmaxf(mx, v);
            }
            mx = fmaxf(mx, __shfl_xor_sync(0xffffffffu, mx, 1));   // warp-sync: all reads done
            float sum = 0.f;
            #pragma unroll
            for (int c=0;c<32;c++){ e[c] = __expf(e[c]-mx); sum += e[c]; }
            sum += __shfl_xor_sync(0xffffffffu, sum, 1);
            float inv = 1.f/sum;
            __syncwarp();
            #pragma unroll
            for (int c=0;c<32;c++) Pw[row*72+half+c] = __float2bfloat16(e[c]*inv);
        }
        __syncwarp();
        // ---- out = P V (16x32) ----
        wmma::fragment<wmma::accumulator,16,16,16,float> acc2[2];
        #pragma unroll
        for (int j=0;j<2;j++) wmma::fill_fragment(acc2[j], 0.f);
        #pragma unroll
        for (int k4=0;k4<4;k4++){
            wmma::fragment<wmma::matrix_a,16,16,16,__nv_bfloat16,wmma::row_major> ap;
            wmma::load_matrix_sync(ap, &Pw[k4*16], 72);
            #pragma unroll
            for (int j=0;j<2;j++){
                wmma::fragment<wmma::matrix_b,16,16,16,__nv_bfloat16,wmma::row_major> bv;
                wmma::load_matrix_sync(bv, &sQ[(size_t)(k4*16)*LDQ + 2*Cdim + h*HD + j*16], LDQ);
                wmma::mma_sync(acc2[j], ap, bv, acc2[j]);
            }
        }
        __syncwarp();     // all Pw reads done before overwriting region
        #pragma unroll
        for (int j=0;j<2;j++)
            wmma::store_matrix_sync(&Sw[j*16], acc2[j], 36, wmma::mem_row_major);
        __syncwarp();
        {
            int row = lane>>1, halfo = (lane&1)*16;
            __nv_bfloat16* op = g_attnout + ((size_t)(wi*64 + n0+row))*Cdim + h*HD + halfo;
            #pragma unroll
            for (int c=0;c<16;c++) op[c] = __float2bfloat16(Sw[row*36 + halfo + c]);
        }
        __syncwarp();
    }
}

// ---------------- channel attention scale s (deterministic partial-sum reduce) ---------------
__global__ void k_s(const float* __restrict__ caw, const float* __restrict__ cab){
    __shared__ float gg[Bsz*Cdim];
    int tid = threadIdx.x;  // 384
    const float* p = g_gappart + (size_t)tid*256;
    float s = 0.f;
    for (int i=0;i<256;i++) s += p[i];
    gg[tid] = s*(1.f/HW);
    __syncthreads();
    int b = tid/Cdim, o = tid%Cdim;
    float acc = cab[o];
    for (int c=0;c<Cdim;c++) acc += gg[b*Cdim+c]*caw[o*Cdim+c];
    g_s[tid] = acc;
}

// ---------------- x1 = x + yattn*s, norm2, emit BHWC tokens for MLP ----------------
__global__ void k_addnorm2(const float* __restrict__ x,
                           const float* __restrict__ nw, const float* __restrict__ nb){
    __shared__ float tile[Cdim][33];
    __shared__ float red1[8][32], red2[8][32];
    __shared__ float s_mu[32], s_ri[32];
    __shared__ float s_w[Cdim], s_b[Cdim], s_sc[Cdim];
    int b = blockIdx.y;
    int p0 = blockIdx.x*32;
    int tid = threadIdx.x;
    if (tid < Cdim){ s_w[tid]=nw[tid]; s_b[tid]=nb[tid]; s_sc[tid]=g_s[b*Cdim+tid]; }
    __syncthreads();
    const float* xb = x + (size_t)b*CHW;
    const __nv_bfloat16* yb = g_yattn + (size_t)b*CHW;
    #pragma unroll
    for (int it=0; it<24; it++){
        int idx = it*256+tid;
        int c = idx>>5, p = idx&31;
        size_t off = (size_t)c*HW + p0+p;
        tile[c][p] = xb[off] + __bfloat162float(yb[off])*s_sc[c];
    }
    __syncthreads();
    int p = tid&31, g = tid>>5;
    float sum=0.f, sq=0.f;
    for (int c=g; c<Cdim; c+=8){ float v=tile[c][p]; sum+=v; sq+=v*v; }
    red1[g][p]=sum; red2[g][p]=sq;
    __syncthreads();
    if (g==0){
        float s=0.f,q=0.f;
        #pragma unroll
        for (int k=0;k<8;k++){ s+=red1[k][p]; q+=red2[k][p]; }
        float mu = s*(1.f/Cdim);
        float var = q*(1.f/Cdim) - mu*mu;
        s_mu[p]=mu; s_ri[p]=rsqrtf(var+1e-6f);
    }
    __syncthreads();
    #pragma unroll
    for (int it=0; it<24; it++){
        int idx = it*256+tid;
        int pp = idx/192, c = idx%192;
        float v = (tile[c][pp]-s_mu[pp])*s_ri[pp]*s_w[c]+s_b[c];
        g_t[((size_t)b*HW + p0+pp)*Cdim + c] = __float2bfloat16(v);
    }
}

// ---------------- launch ----------------
extern "C" void kernel_launch(void* const* d_in, const int* in_sizes, int n_in,
                              void* d_out, int out_size){
    const float* x    = (const float*)d_in[0];
    const float* n1w  = (const float*)d_in[1];
    const float* n1b  = (const float*)d_in[2];
    const float* qkvw = (const float*)d_in[3];
    const float* qkvb = (const float*)d_in[4];
    const float* projw= (const float*)d_in[5];
    const float* projb= (const float*)d_in[6];
    const float* rpb  = (const float*)d_in[7];
    const float* caw  = (const float*)d_in[8];
    const float* cab  = (const float*)d_in[9];
    const float* n2w  = (const float*)d_in[10];
    const float* n2b  = (const float*)d_in[11];
    const float* fc1w = (const float*)d_in[12];
    const float* fc1b = (const float*)d_in[13];
    const float* fc2w = (const float*)d_in[14];
    const float* fc2b = (const float*)d_in[15];
    float* out = (float*)d_out;

    const int smG = 192*72*2 + 2*256*72*2;   // 101376 -> 2 blocks/SM
    static bool attr_done = false;
    if (!attr_done){
        cudaFuncSetAttribute(k_attn,        cudaFuncAttributeMaxDynamicSharedMemorySize, ATT_SM);
        cudaFuncSetAttribute(k_gemm_qkv,    cudaFuncAttributeMaxDynamicSharedMemorySize, smG);
        cudaFuncSetAttribute(k_gemm_proj_f, cudaFuncAttributeMaxDynamicSharedMemorySize, smG);
        cudaFuncSetAttribute(k_gemm_fc1,    cudaFuncAttributeMaxDynamicSharedMemorySize, smG);
        cudaFuncSetAttribute(k_gemm_fc2_f,  cudaFuncAttributeMaxDynamicSharedMemorySize, smG);
        attr_done = true;
    }

    k_conv_all  <<<(Cdim*C3+255)/256, 256>>>(qkvw, qkvb, projw, fc1w, fc2w);
    k_norm1_roll<<<dim3(HW/32, Bsz), 256>>>(x, n1w, n1b);
    k_win_gather<<<NWIN, 256>>>();
    k_gemm_qkv  <<<dim3(NTOK/256, C3/64),   256, smG>>>();
    k_attn      <<<NWIN, 256, ATT_SM>>>(rpb);
    k_gemm_proj_f<<<dim3(NTOK/256, Cdim/64),256, smG>>>(projb);
    k_s         <<<1, 384>>>(caw, cab);
    k_addnorm2  <<<dim3(HW/32, Bsz), 256>>>(x, n2w, n2b);
    k_gemm_fc1  <<<dim3(NTOK/256, HID/64),  256, smG>>>(fc1b);
    k_gemm_fc2_f<<<dim3(NTOK/256, Cdim/64), 256, smG>>>(fc2b, x, out);
}

// round 15
// speedup vs baseline: 1.1331x; 1.1331x over previous
#include <cuda_runtime.h>
#include <cuda_bf16.h>
#include <mma.h>
#include <cstdint>

using namespace nvcuda;

#define Bsz   2
#define Cdim  192
#define Hdim  256
#define Wdim  256
#define HW    65536
#define CHW   12582912
#define NHEAD 6
#define HD    32
#define NTOK  131072
#define C3    576
#define HID   384
#define NWIN  2048

// ---------------- scratch (device globals; no allocation allowed) ----------------
__device__ __nv_bfloat16 g_roll[(size_t)Bsz*CHW];
__device__ __nv_bfloat16 g_win[(size_t)NTOK*Cdim];
__device__ __nv_bfloat16 g_qkv[(size_t)NTOK*C3];
__device__ __nv_bfloat16 g_attnout[(size_t)NTOK*Cdim];
__device__ __nv_bfloat16 g_yattn[(size_t)Bsz*CHW];
__device__ float         g_gappart[(size_t)Bsz*Cdim*256];
__device__ float         g_s[Bsz*Cdim];
__device__ __nv_bfloat16 g_t[(size_t)NTOK*Cdim];
__device__ __nv_bfloat16 g_h[(size_t)NTOK*HID];
__device__ __nv_bfloat16 g_wqkv[Cdim*C3];
__device__ float         g_bqkv[C3];
__device__ __nv_bfloat16 g_wproj[Cdim*Cdim];
__device__ __nv_bfloat16 g_wfc1[Cdim*HID];
__device__ __nv_bfloat16 g_wfc2[HID*Cdim];

// ---------------- helpers ----------------
__device__ __forceinline__ uint32_t smem_u32(const void* p){
    uint32_t a;
    asm("{ .reg .u64 t; cvta.to.shared.u64 t, %1; cvt.u32.u64 %0, t; }" : "=r"(a) : "l"(p));
    return a;
}
__device__ __forceinline__ void cp16(uint32_t dst, const void* src){
    asm volatile("cp.async.cg.shared.global [%0], [%1], 16;" :: "r"(dst), "l"(src));
}
#define CP_COMMIT() asm volatile("cp.async.commit_group;" ::: "memory")
#define CP_WAIT0()  asm volatile("cp.async.wait_group 0;" ::: "memory")

// ---------------- all weight conversions in one kernel (scale folded into q cols) -------------
__global__ void k_conv_all(const float* __restrict__ qw, const float* __restrict__ qb,
                           const float* __restrict__ pw, const float* __restrict__ f1,
                           const float* __restrict__ f2){
    int i = blockIdx.x*256 + threadIdx.x;
    const float sc = 0.17677669529663687f; // 32^-0.5
    if (i < Cdim*C3){
        int o = i % C3;
        float f = qw[i];
        if (o < Cdim) f *= sc;
        g_wqkv[i] = __float2bfloat16(f);
    }
    if (i < C3){
        float f = qb[i];
        if (i < Cdim) f *= sc;
        g_bqkv[i] = f;
    }
    if (i < Cdim*Cdim) g_wproj[i] = __float2bfloat16(pw[i]);
    if (i < Cdim*HID)  g_wfc1[i]  = __float2bfloat16(f1[i]);
    if (i < HID*Cdim)  g_wfc2[i]  = __float2bfloat16(f2[i]);
}

// ---------------- norm1 (over C per pixel) fused with the "buggy" flat roll ----------------
__global__ void k_norm1_roll(const float* __restrict__ x,
                             const float* __restrict__ nw, const float* __restrict__ nb){
    __shared__ float tile[Cdim][33];
    __shared__ float red1[8][32], red2[8][32];
    __shared__ float s_mu[32], s_ri[32];
    __shared__ float s_w[Cdim], s_b[Cdim];
    int b = blockIdx.y;
    int p0 = blockIdx.x * 32;
    const float* xb = x + (size_t)b*CHW;
    int tid = threadIdx.x;
    if (tid < Cdim){ s_w[tid]=nw[tid]; s_b[tid]=nb[tid]; }
    #pragma unroll
    for (int it=0; it<24; it++){
        int idx = it*256+tid;
        int c = idx>>5, p = idx&31;
        tile[c][p] = xb[(size_t)c*HW + p0 + p];
    }
    __syncthreads();
    int p = tid&31, g = tid>>5;
    float sum=0.f, sq=0.f;
    for (int c=g; c<Cdim; c+=8){ float v=tile[c][p]; sum+=v; sq+=v*v; }
    red1[g][p]=sum; red2[g][p]=sq;
    __syncthreads();
    if (g==0){
        float s=0.f,q=0.f;
        #pragma unroll
        for (int k=0;k<8;k++){ s+=red1[k][p]; q+=red2[k][p]; }
        float mu = s*(1.f/Cdim);
        float var = q*(1.f/Cdim) - mu*mu;
        s_mu[p]=mu; s_ri[p]=rsqrtf(var+1e-6f);
    }
    __syncthreads();
    __nv_bfloat16* rb = g_roll + (size_t)b*CHW;
    #pragma unroll
    for (int it=0; it<24; it++){
        int idx = it*256+tid;
        int c = idx>>5, pp = idx&31;
        float v = (tile[c][pp]-s_mu[pp])*s_ri[pp]*s_w[c]+s_b[c];
        int f = c*HW + p0 + pp;
        int i = f/49152; int r = f - i*49152; int j = r/192; int k = r - j*192;
        int t = ((i-4)&255)*49152 + ((j-4)&255)*192 + k;
        rb[t] = __float2bfloat16(v);
    }
}

// ---------------- window partition: rolled BCHW -> (win, n, c) tokens ----------------
__global__ void k_win_gather(){
    __shared__ __nv_bfloat16 s[96][66];
    int wi = blockIdx.x; int tid = threadIdx.x;
    int b = wi>>10, gh=(wi&1023)>>5, gw=wi&31;
    const __nv_bfloat16* rb = g_roll + (size_t)b*CHW;
    size_t base = (size_t)(gh*8)*256 + gw*8;
    for (int chunk=0; chunk<2; chunk++){
        int c0 = chunk*96;
        #pragma unroll
        for (int it=0; it<24; it++){
            int idx = it*256+tid;
            int cl = idx>>6, n = idx&63;
            s[cl][n] = rb[(size_t)(c0+cl)*HW + base + (n>>3)*256 + (n&7)];
        }
        __syncthreads();
        #pragma unroll
        for (int it=0; it<24; it++){
            int idx = it*256+tid;
            int n = idx/96, cl = idx%96;
            g_win[((size_t)wi*64+n)*Cdim + c0 + cl] = s[cl][n];
        }
        __syncthreads();
    }
}

// ---------------- GEMM mainloop: 256x64 CTA tile, 8 warps x (64x32), ldm=72, cp.async --------
// K processed in 192-wide segments: B segment resident, A double-buffered in 64-chunks.
// Returns smem Cs[256][68] (raw accum, pre-bias), after syncthreads.
template<int K, int N>
__device__ __forceinline__ float* gemm_main(const __nv_bfloat16* __restrict__ A,
                                            const __nv_bfloat16* __restrict__ Bm){
    extern __shared__ __align__(16) char sm[];
    __nv_bfloat16* Bs = (__nv_bfloat16*)sm;                       // [192][72]
    __nv_bfloat16* As = (__nv_bfloat16*)(sm + 192*144);           // [2][256][72]
    float*         Cs = (float*)(sm + 192*144);                   // [256][68] (aliases As)
    const uint32_t sB = smem_u32(sm);
    const uint32_t sA = sB + 192*144;
    const int tid = threadIdx.x;
    const int m0 = blockIdx.x*256, n0 = blockIdx.y*64;
    const int warp = tid>>5, wr = warp>>1, wc = warp&1;

    auto loadB = [&](int s){
        #pragma unroll
        for (int it=0; it<6; it++){
            int idx = it*256+tid;
            int row = idx>>3, u = idx&7;
            cp16(sB + row*144 + u*16, &Bm[(size_t)(s*192+row)*N + n0 + u*8]);
        }
    };
    auto loadA = [&](int s, int c, int buf){
        #pragma unroll
        for (int it=0; it<8; it++){
            int idx = it*256+tid;
            int row = idx>>3, u = idx&7;
            cp16(sA + (buf*256+row)*144 + u*16,
                 &A[(size_t)(m0+row)*K + s*192 + c*64 + u*8]);
        }
    };

    wmma::fragment<wmma::accumulator,16,16,16,float> acc[4][2];
    #pragma unroll
    for (int i=0;i<4;i++)
        #pragma unroll
        for (int j=0;j<2;j++) wmma::fill_fragment(acc[i][j], 0.f);

    constexpr int NS = K/192;
    #pragma unroll
    for (int s=0;s<NS;s++){
        loadB(s);
        loadA(s,0,0);
        CP_COMMIT(); CP_WAIT0();
        __syncthreads();
        #pragma unroll
        for (int c=0;c<3;c++){
            if (c<2){ loadA(s,c+1,(c+1)&1); CP_COMMIT(); }
            int buf = c&1;
            #pragma unroll
            for (int kk=0;kk<64;kk+=16){
                wmma::fragment<wmma::matrix_a,16,16,16,__nv_bfloat16,wmma::row_major> af[4];
                wmma::fragment<wmma::matrix_b,16,16,16,__nv_bfloat16,wmma::row_major> bf[2];
                #pragma unroll
                for (int i=0;i<4;i++)
                    wmma::load_matrix_sync(af[i], &As[(size_t)(buf*256+wr*64+i*16)*72 + kk], 72);
                #pragma unroll
                for (int j=0;j<2;j++)
                    wmma::load_matrix_sync(bf[j], &Bs[(size_t)(c*64+kk)*72 + wc*32+j*16], 72);
                #pragma unroll
                for (int i=0;i<4;i++)
                    #pragma unroll
                    for (int j=0;j<2;j++)
                        wmma::mma_sync(acc[i][j], af[i], bf[j], acc[i][j]);
            }
            CP_WAIT0();
            __syncthreads();
        }
    }
    #pragma unroll
    for (int i=0;i<4;i++)
        #pragma unroll
        for (int j=0;j<2;j++)
            wmma::store_matrix_sync(&Cs[(size_t)(wr*64+i*16)*68 + wc*32+j*16], acc[i][j], 68, wmma::mem_row_major);
    __syncthreads();
    return Cs;
}

// qkv: plain bf16 epilogue
__global__ void __launch_bounds__(256,2) k_gemm_qkv(){
    float* Cs = gemm_main<Cdim,C3>(g_win, g_wqkv);
    const int tid = threadIdx.x;
    const int m0 = blockIdx.x*256, n0 = blockIdx.y*64;
    #pragma unroll
    for (int it=0; it<64; it++){
        int idx = it*256+tid;
        int r = idx>>6, cc = idx&63;
        float v = Cs[(size_t)r*68+cc] + g_bqkv[n0+cc];
        g_qkv[(size_t)(m0+r)*C3 + n0 + cc] = __float2bfloat16(v);
    }
}

// fc1: gelu epilogue
__global__ void __launch_bounds__(256,2) k_gemm_fc1(const float* __restrict__ bias){
    float* Cs = gemm_main<Cdim,HID>(g_t, g_wfc1);
    const int tid = threadIdx.x;
    const int m0 = blockIdx.x*256, n0 = blockIdx.y*64;
    #pragma unroll
    for (int it=0; it<64; it++){
        int idx = it*256+tid;
        int r = idx>>6, cc = idx&63;
        float v = Cs[(size_t)r*68+cc] + bias[n0+cc];
        v = 0.5f*v*(1.f+erff(v*0.70710678118654752f));
        g_h[(size_t)(m0+r)*HID + n0 + cc] = __float2bfloat16(v);
    }
}

// proj: fused window-reverse scatter into BCHW yattn + deterministic gap partials
__global__ void __launch_bounds__(256,2) k_gemm_proj_f(const float* __restrict__ bias){
    float* Cs = gemm_main<Cdim,Cdim>(g_attnout, g_wproj);
    __shared__ float sgap[4][64];
    const int tid = threadIdx.x;
    const int m0 = blockIdx.x*256, n0 = blockIdx.y*64;
    const int w0 = m0/64;                 // first of 4 windows (same batch, no straddle)
    const int b  = w0>>10;
    // scatter: token (wi, n) -> pixel b,c,(gh*8+(n>>3))*256 + gw*8+(n&7)
    const int w = (tid>>3)&3, q = tid&7, grp32 = tid>>5;
    {
        int wi = w0 + w;
        int gh = (wi&1023)>>5, gw = wi&31;
        size_t pixbase = (size_t)b*CHW + (size_t)gh*2048 + gw*8 + q;
        #pragma unroll
        for (int it=0; it<64; it++){
            int combo = it*8 + grp32;       // 0..511 = cc*8 + i
            int cc = combo>>3, i = combo&7;
            int r = w*64 + i*8 + q;
            float v = Cs[(size_t)r*68+cc] + bias[n0+cc];
            g_yattn[pixbase + (size_t)(n0+cc)*HW + i*256] = __float2bfloat16(v);
        }
    }
    // gap partials (sum of bf16-rounded outputs per channel over this tile's 256 tokens)
    {
        int cc = tid&63, grp = tid>>6;
        float s = 0.f;
        float bb = bias[n0+cc];
        #pragma unroll
        for (int k=0;k<64;k++){
            int r = grp*64+k;
            s += __bfloat162float(__float2bfloat16(Cs[(size_t)r*68+cc] + bb));
        }
        sgap[grp][cc] = s;
        __syncthreads();
        if (tid < 64){
            float t = sgap[0][tid]+sgap[1][tid]+sgap[2][tid]+sgap[3][tid];
            g_gappart[(size_t)(b*Cdim + n0 + tid)*256 + (blockIdx.x & 255)] = t;
        }
    }
}

// fc2: fused final residual  out = x + yattn*s + fc2(h)
__global__ void __launch_bounds__(256,2) k_gemm_fc2_f(const float* __restrict__ bias,
                                                      const float* __restrict__ x,
                                                      float* __restrict__ out){
    float* Cs = gemm_main<HID,Cdim>(g_h, g_wfc2);
    __shared__ float s_sc[64];
    const int tid = threadIdx.x;
    const int m0 = blockIdx.x*256, n0 = blockIdx.y*64;
    const int b = m0>>16, p0 = m0&65535;
    if (tid < 64) s_sc[tid] = g_s[b*Cdim + n0 + tid];
    __syncthreads();
    #pragma unroll
    for (int it=0; it<64; it++){
        int idx = it*256+tid;
        int cc = idx>>8, pp = idx&255;
        float v = Cs[(size_t)pp*68+cc] + bias[n0+cc];
        size_t off = (size_t)b*CHW + (size_t)(n0+cc)*HW + p0 + pp;
        float y = __bfloat162float(g_yattn[off]);
        out[off] = x[off] + y*s_sc[cc] + v;
    }
}

// ---------------- fused window attention, WMMA: 2 blocks/SM (112.5KB smem) ----------------
#define LDQ 584
#define ATT_SS  74752
#define ATT_RPB 109568
#define ATT_CLS 112272
#define ATT_SM  112528
__global__ void __launch_bounds__(256) k_attn(const float* __restrict__ rpb){
    extern __shared__ __align__(16) char sm[];
    __nv_bfloat16* sQ   = (__nv_bfloat16*)sm;                   // [64][584]
    float*         sS   = (float*)(sm + ATT_SS);                // [8][16*68]  (P aliases this)
    __nv_bfloat16* sRpb = (__nv_bfloat16*)(sm + ATT_RPB);       // [6*225]
    int*           sCls = (int*)(sm + ATT_CLS);                 // [64]
    int wi = blockIdx.x;
    int tid = threadIdx.x, warp = tid>>5, lane = tid&31;
    int gh = (wi & 1023) >> 5, gw = wi & 31;

    const __nv_bfloat16* qkvb = g_qkv + (size_t)wi*64*C3;
    #pragma unroll
    for (int it=0; it<18; it++){
        int idx = it*256+tid;
        int row = idx/72, u = idx%72;
        *(uint4*)&sQ[row*LDQ + u*8] = *(const uint4*)&qkvb[(size_t)row*C3 + u*8];
    }
    for (int i=tid; i<NHEAD*225; i+=256){
        int h = i/225, p = i%225;
        sRpb[h*225+p] = __float2bfloat16(rpb[p*NHEAD + h]);
    }
    if (tid < 64){
        int i = tid>>3, j = tid&7;
        int hg = gh*8+i, wg = gw*8+j;
        int rh = hg < 248 ? 0 : (hg < 252 ? 1 : 2);
        int rw = wg < 248 ? 0 : (wg < 252 ? 1 : 2);
        sCls[tid] = rh*3+rw;
    }
    __syncthreads();

    #pragma unroll
    for (int r=0; r<3; r++){
        int task = warp + 8*r;            // 0..23
        int h = task>>2, strip = task&3, n0 = strip*16;
        float*         Sw = sS + warp*16*68;
        __nv_bfloat16* Pw = (__nv_bfloat16*)Sw;     // alias: reads complete before writes
        // ---- S = Q Kt (16x64) ----
        wmma::fragment<wmma::accumulator,16,16,16,float> acc[4];
        #pragma unroll
        for (int j=0;j<4;j++) wmma::fill_fragment(acc[j], 0.f);
        #pragma unroll
        for (int kk=0; kk<32; kk+=16){
            wmma::fragment<wmma::matrix_a,16,16,16,__nv_bfloat16,wmma::row_major> aq;
            wmma::load_matrix_sync(aq, &sQ[(size_t)n0*LDQ + h*HD + kk], LDQ);
            #pragma unroll
            for (int j=0;j<4;j++){
                wmma::fragment<wmma::matrix_b,16,16,16,__nv_bfloat16,wmma::col_major> bk;
                wmma::load_matrix_sync(bk, &sQ[(size_t)(j*16)*LDQ + Cdim + h*HD + kk], LDQ);
                wmma::mma_sync(acc[j], aq, bk, acc[j]);
            }
        }
        #pragma unroll
        for (int j=0;j<4;j++)
            wmma::store_matrix_sync(&Sw[j*16], acc[j], 68, wmma::mem_row_major);
        __syncwarp();
        // ---- softmax with rpb bias + shift mask (lane: one row half) ----
        {
            int row = lane>>1, half = (lane&1)*32;
            int n = n0+row, ni = n>>3, nj = n&7;
            int cn = sCls[n];
            const __nv_bfloat16* rh = sRpb + h*225;
            float e[32]; float mx = -1e30f;
            #pragma unroll
            for (int c=0;c<32;c++){
                int m = half+c;
                float v = Sw[row*68+m] + __bfloat162float(rh[(ni-(m>>3)+7)*15 + (nj-(m&7)+7)]);
                if (cn != sCls[m]) v -= 100.f;
                e[c]=v; mx = fmaxf(mx, v);
            }
            mx = fmaxf(mx, __shfl_xor_sync(0xffffffffu, mx, 1));   // warp-sync: all reads done
            float sum = 0.f;
            #pragma unroll
            for (int c=0;c<32;c++){ e[c] = __expf(e[c]-mx); sum += e[c]; }
            sum += __shfl_xor_sync(0xffffffffu, sum, 1);
            float inv = 1.f/sum;
            __syncwarp();
            #pragma unroll
            for (int c=0;c<32;c++) Pw[row*72+half+c] = __float2bfloat16(e[c]*inv);
        }
        __syncwarp();
        // ---- out = P V (16x32) ----
        wmma::fragment<wmma::accumulator,16,16,16,float> acc2[2];
        #pragma unroll
        for (int j=0;j<2;j++) wmma::fill_fragment(acc2[j], 0.f);
        #pragma unroll
        for (int k4=0;k4<4;k4++){
            wmma::fragment<wmma::matrix_a,16,16,16,__nv_bfloat16,wmma::row_major> ap;
            wmma::load_matrix_sync(ap, &Pw[k4*16], 72);
            #pragma unroll
            for (int j=0;j<2;j++){
                wmma::fragment<wmma::matrix_b,16,16,16,__nv_bfloat16,wmma::row_major> bv;
                wmma::load_matrix_sync(bv, &sQ[(size_t)(k4*16)*LDQ + 2*Cdim + h*HD + j*16], LDQ);
                wmma::mma_sync(acc2[j], ap, bv, acc2[j]);
            }
        }
        __syncwarp();     // all Pw reads done before overwriting region
        #pragma unroll
        for (int j=0;j<2;j++)
            wmma::store_matrix_sync(&Sw[j*16], acc2[j], 36, wmma::mem_row_major);
        __syncwarp();
        {
            int row = lane>>1, halfo = (lane&1)*16;
            __nv_bfloat16* op = g_attnout + ((size_t)(wi*64 + n0+row))*Cdim + h*HD + halfo;
            #pragma unroll
            for (int c=0;c<16;c++) op[c] = __float2bfloat16(Sw[row*36 + halfo + c]);
        }
        __syncwarp();
    }
}

// ---------------- channel attention scale s (deterministic partial-sum reduce) ---------------
__global__ void k_s(const float* __restrict__ caw, const float* __restrict__ cab){
    __shared__ float gg[Bsz*Cdim];
    int tid = threadIdx.x;  // 384
    const float* p = g_gappart + (size_t)tid*256;
    float s = 0.f;
    for (int i=0;i<256;i++) s += p[i];
    gg[tid] = s*(1.f/HW);
    __syncthreads();
    int b = tid/Cdim, o = tid%Cdim;
    float acc = cab[o];
    for (int c=0;c<Cdim;c++) acc += gg[b*Cdim+c]*caw[o*Cdim+c];
    g_s[tid] = acc;
}

// ---------------- x1 = x + yattn*s, norm2, emit BHWC tokens for MLP ----------------
__global__ void k_addnorm2(const float* __restrict__ x,
                           const float* __restrict__ nw, const float* __restrict__ nb){
    __shared__ float tile[Cdim][33];
    __shared__ float red1[8][32], red2[8][32];
    __shared__ float s_mu[32], s_ri[32];
    __shared__ float s_w[Cdim], s_b[Cdim], s_sc[Cdim];
    int b = blockIdx.y;
    int p0 = blockIdx.x*32;
    int tid = threadIdx.x;
    if (tid < Cdim){ s_w[tid]=nw[tid]; s_b[tid]=nb[tid]; s_sc[tid]=g_s[b*Cdim+tid]; }
    __syncthreads();
    const float* xb = x + (size_t)b*CHW;
    const __nv_bfloat16* yb = g_yattn + (size_t)b*CHW;
    #pragma unroll
    for (int it=0; it<24; it++){
        int idx = it*256+tid;
        int c = idx>>5, p = idx&31;
        size_t off = (size_t)c*HW + p0+p;
        tile[c][p] = xb[off] + __bfloat162float(yb[off])*s_sc[c];
    }
    __syncthreads();
    int p = tid&31, g = tid>>5;
    float sum=0.f, sq=0.f;
    for (int c=g; c<Cdim; c+=8){ float v=tile[c][p]; sum+=v; sq+=v*v; }
    red1[g][p]=sum; red2[g][p]=sq;
    __syncthreads();
    if (g==0){
        float s=0.f,q=0.f;
        #pragma unroll
        for (int k=0;k<8;k++){ s+=red1[k][p]; q+=red2[k][p]; }
        float mu = s*(1.f/Cdim);
        float var = q*(1.f/Cdim) - mu*mu;
        s_mu[p]=mu; s_ri[p]=rsqrtf(var+1e-6f);
    }
    __syncthreads();
    #pragma unroll
    for (int it=0; it<24; it++){
        int idx = it*256+tid;
        int pp = idx/192, c = idx%192;
        float v = (tile[c][pp]-s_mu[pp])*s_ri[pp]*s_w[c]+s_b[c];
        g_t[((size_t)b*HW + p0+pp)*Cdim + c] = __float2bfloat16(v);
    }
}

// ---------------- launch ----------------
extern "C" void kernel_launch(void* const* d_in, const int* in_sizes, int n_in,
                              void* d_out, int out_size){
    const float* x    = (const float*)d_in[0];
    const float* n1w  = (const float*)d_in[1];
    const float* n1b  = (const float*)d_in[2];
    const float* qkvw = (const float*)d_in[3];
    const float* qkvb = (const float*)d_in[4];
    const float* projw= (const float*)d_in[5];
    const float* projb= (const float*)d_in[6];
    const float* rpb  = (const float*)d_in[7];
    const float* caw  = (const float*)d_in[8];
    const float* cab  = (const float*)d_in[9];
    const float* n2w  = (const float*)d_in[10];
    const float* n2b  = (const float*)d_in[11];
    const float* fc1w = (const float*)d_in[12];
    const float* fc1b = (const float*)d_in[13];
    const float* fc2w = (const float*)d_in[14];
    const float* fc2b = (const float*)d_in[15];
    float* out = (float*)d_out;

    const int smG = 192*144 + 2*256*144;   // 101376 -> 2 blocks/SM
    static bool attr_done = false;
    if (!attr_done){
        cudaFuncSetAttribute(k_attn,        cudaFuncAttributeMaxDynamicSharedMemorySize, ATT_SM);
        cudaFuncSetAttribute(k_gemm_qkv,    cudaFuncAttributeMaxDynamicSharedMemorySize, smG);
        cudaFuncSetAttribute(k_gemm_proj_f, cudaFuncAttributeMaxDynamicSharedMemorySize, smG);
        cudaFuncSetAttribute(k_gemm_fc1,    cudaFuncAttributeMaxDynamicSharedMemorySize, smG);
        cudaFuncSetAttribute(k_gemm_fc2_f,  cudaFuncAttributeMaxDynamicSharedMemorySize, smG);
        attr_done = true;
    }

    k_conv_all  <<<(Cdim*C3+255)/256, 256>>>(qkvw, qkvb, projw, fc1w, fc2w);
    k_norm1_roll<<<dim3(HW/32, Bsz), 256>>>(x, n1w, n1b);
    k_win_gather<<<NWIN, 256>>>();
    k_gemm_qkv  <<<dim3(NTOK/256, C3/64),   256, smG>>>();
    k_attn      <<<NWIN, 256, ATT_SM>>>(rpb);
    k_gemm_proj_f<<<dim3(NTOK/256, Cdim/64),256, smG>>>(projb);
    k_s         <<<1, 384>>>(caw, cab);
    k_addnorm2  <<<dim3(HW/32, Bsz), 256>>>(x, n2w, n2b);
    k_gemm_fc1  <<<dim3(NTOK/256, HID/64),  256, smG>>>(fc1b);
    k_gemm_fc2_f<<<dim3(NTOK/256, Cdim/64), 256, smG>>>(fc2b, x, out);
}

// round 16
// speedup vs baseline: 1.2316x; 1.0869x over previous
#include <cuda_runtime.h>
#include <cuda_bf16.h>
#include <mma.h>
#include <cstdint>

using namespace nvcuda;

#define Bsz   2
#define Cdim  192
#define Hdim  256
#define Wdim  256
#define HW    65536
#define CHW   12582912
#define NHEAD 6
#define HD    32
#define NTOK  131072
#define C3    576
#define HID   384
#define NWIN  2048

// ---------------- scratch (device globals; no allocation allowed) ----------------
__device__ __nv_bfloat16 g_roll[(size_t)Bsz*CHW];
__device__ __nv_bfloat16 g_win[(size_t)NTOK*Cdim];
__device__ __nv_bfloat16 g_qkv[(size_t)NTOK*C3];
__device__ __nv_bfloat16 g_attnout[(size_t)NTOK*Cdim];
__device__ __nv_bfloat16 g_yattn[(size_t)Bsz*CHW];
__device__ float         g_gappart[(size_t)Bsz*Cdim*256];
__device__ float         g_s[Bsz*Cdim];
__device__ __nv_bfloat16 g_t[(size_t)NTOK*Cdim];
__device__ __nv_bfloat16 g_h[(size_t)NTOK*HID];
__device__ __nv_bfloat16 g_wqkv[Cdim*C3];
__device__ float         g_bqkv[C3];
__device__ __nv_bfloat16 g_wproj[Cdim*Cdim];
__device__ __nv_bfloat16 g_wfc1[Cdim*HID];
__device__ __nv_bfloat16 g_wfc2[HID*Cdim];
__device__ __nv_bfloat16 g_bias[NHEAD*64*64];   // [h][n][m] rpb bias table

// ---------------- helpers ----------------
__device__ __forceinline__ uint32_t smem_u32(const void* p){
    uint32_t a;
    asm("{ .reg .u64 t; cvta.to.shared.u64 t, %1; cvt.u32.u64 %0, t; }" : "=r"(a) : "l"(p));
    return a;
}
__device__ __forceinline__ void cp16(uint32_t dst, const void* src){
    asm volatile("cp.async.cg.shared.global [%0], [%1], 16;" :: "r"(dst), "l"(src));
}
#define CP_COMMIT() asm volatile("cp.async.commit_group;" ::: "memory")
#define CP_WAIT0()  asm volatile("cp.async.wait_group 0;" ::: "memory")

// ---------------- weight conversions + rpb bias table ----------------
__global__ void k_conv_all(const float* __restrict__ qw, const float* __restrict__ qb,
                           const float* __restrict__ pw, const float* __restrict__ f1,
                           const float* __restrict__ f2, const float* __restrict__ rpb){
    int i = blockIdx.x*256 + threadIdx.x;
    const float sc = 0.17677669529663687f; // 32^-0.5
    if (i < Cdim*C3){
        int o = i % C3;
        float f = qw[i];
        if (o < Cdim) f *= sc;
        g_wqkv[i] = __float2bfloat16(f);
    }
    if (i < C3){
        float f = qb[i];
        if (i < Cdim) f *= sc;
        g_bqkv[i] = f;
    }
    if (i < Cdim*Cdim) g_wproj[i] = __float2bfloat16(pw[i]);
    if (i < Cdim*HID)  g_wfc1[i]  = __float2bfloat16(f1[i]);
    if (i < HID*Cdim)  g_wfc2[i]  = __float2bfloat16(f2[i]);
    if (i < NHEAD*64*64){
        int h = i >> 12, r = i & 4095;
        int n = r >> 6, m = r & 63;
        int idx = ((n>>3)-(m>>3)+7)*15 + ((n&7)-(m&7)+7);
        g_bias[i] = __float2bfloat16(rpb[idx*NHEAD + h]);
    }
}

// ---------------- norm1 (over C per pixel) fused with the "buggy" flat roll ----------------
__global__ void k_norm1_roll(const float* __restrict__ x,
                             const float* __restrict__ nw, const float* __restrict__ nb){
    __shared__ float tile[Cdim][33];
    __shared__ float red1[8][32], red2[8][32];
    __shared__ float s_mu[32], s_ri[32];
    __shared__ float s_w[Cdim], s_b[Cdim];
    int b = blockIdx.y;
    int p0 = blockIdx.x * 32;
    const float* xb = x + (size_t)b*CHW;
    int tid = threadIdx.x;
    if (tid < Cdim){ s_w[tid]=nw[tid]; s_b[tid]=nb[tid]; }
    #pragma unroll
    for (int it=0; it<24; it++){
        int idx = it*256+tid;
        int c = idx>>5, p = idx&31;
        tile[c][p] = xb[(size_t)c*HW + p0 + p];
    }
    __syncthreads();
    int p = tid&31, g = tid>>5;
    float sum=0.f, sq=0.f;
    for (int c=g; c<Cdim; c+=8){ float v=tile[c][p]; sum+=v; sq+=v*v; }
    red1[g][p]=sum; red2[g][p]=sq;
    __syncthreads();
    if (g==0){
        float s=0.f,q=0.f;
        #pragma unroll
        for (int k=0;k<8;k++){ s+=red1[k][p]; q+=red2[k][p]; }
        float mu = s*(1.f/Cdim);
        float var = q*(1.f/Cdim) - mu*mu;
        s_mu[p]=mu; s_ri[p]=rsqrtf(var+1e-6f);
    }
    __syncthreads();
    __nv_bfloat16* rb = g_roll + (size_t)b*CHW;
    #pragma unroll
    for (int it=0; it<24; it++){
        int idx = it*256+tid;
        int c = idx>>5, pp = idx&31;
        float v = (tile[c][pp]-s_mu[pp])*s_ri[pp]*s_w[c]+s_b[c];
        int f = c*HW + p0 + pp;
        int i = f/49152; int r = f - i*49152; int j = r/192; int k = r - j*192;
        int t = ((i-4)&255)*49152 + ((j-4)&255)*192 + k;
        rb[t] = __float2bfloat16(v);
    }
}

// ---------------- window partition: rolled BCHW -> (win, n, c) tokens ----------------
__global__ void k_win_gather(){
    __shared__ __nv_bfloat16 s[96][66];
    int wi = blockIdx.x; int tid = threadIdx.x;
    int b = wi>>10, gh=(wi&1023)>>5, gw=wi&31;
    const __nv_bfloat16* rb = g_roll + (size_t)b*CHW;
    size_t base = (size_t)(gh*8)*256 + gw*8;
    for (int chunk=0; chunk<2; chunk++){
        int c0 = chunk*96;
        #pragma unroll
        for (int it=0; it<24; it++){
            int idx = it*256+tid;
            int cl = idx>>6, n = idx&63;
            s[cl][n] = rb[(size_t)(c0+cl)*HW + base + (n>>3)*256 + (n&7)];
        }
        __syncthreads();
        #pragma unroll
        for (int it=0; it<24; it++){
            int idx = it*256+tid;
            int n = idx/96, cl = idx%96;
            g_win[((size_t)wi*64+n)*Cdim + c0 + cl] = s[cl][n];
        }
        __syncthreads();
    }
}

// ---------------- GEMM mainloop: 256x64 CTA tile, 8 warps x (64x32), ldm=72, cp.async --------
// Grid: (N/64, NTOK/256) — N-tiles fastest so co-resident blocks share A rows (L2 reuse).
template<int K, int N>
__device__ __forceinline__ float* gemm_main(const __nv_bfloat16* __restrict__ A,
                                            const __nv_bfloat16* __restrict__ Bm){
    extern __shared__ __align__(16) char sm[];
    __nv_bfloat16* Bs = (__nv_bfloat16*)sm;                       // [192][72]
    __nv_bfloat16* As = (__nv_bfloat16*)(sm + 192*144);           // [2][256][72]
    float*         Cs = (float*)(sm + 192*144);                   // [256][68] (aliases As)
    const uint32_t sB = smem_u32(sm);
    const uint32_t sA = sB + 192*144;
    const int tid = threadIdx.x;
    const int m0 = blockIdx.y*256, n0 = blockIdx.x*64;
    const int warp = tid>>5, wr = warp>>1, wc = warp&1;

    auto loadB = [&](int s){
        #pragma unroll
        for (int it=0; it<6; it++){
            int idx = it*256+tid;
            int row = idx>>3, u = idx&7;
            cp16(sB + row*144 + u*16, &Bm[(size_t)(s*192+row)*N + n0 + u*8]);
        }
    };
    auto loadA = [&](int s, int c, int buf){
        #pragma unroll
        for (int it=0; it<8; it++){
            int idx = it*256+tid;
            int row = idx>>3, u = idx&7;
            cp16(sA + (buf*256+row)*144 + u*16,
                 &A[(size_t)(m0+row)*K + s*192 + c*64 + u*8]);
        }
    };

    wmma::fragment<wmma::accumulator,16,16,16,float> acc[4][2];
    #pragma unroll
    for (int i=0;i<4;i++)
        #pragma unroll
        for (int j=0;j<2;j++) wmma::fill_fragment(acc[i][j], 0.f);

    constexpr int NS = K/192;
    #pragma unroll
    for (int s=0;s<NS;s++){
        loadB(s);
        loadA(s,0,0);
        CP_COMMIT(); CP_WAIT0();
        __syncthreads();
        #pragma unroll
        for (int c=0;c<3;c++){
            if (c<2){ loadA(s,c+1,(c+1)&1); CP_COMMIT(); }
            int buf = c&1;
            #pragma unroll
            for (int kk=0;kk<64;kk+=16){
                wmma::fragment<wmma::matrix_a,16,16,16,__nv_bfloat16,wmma::row_major> af[4];
                wmma::fragment<wmma::matrix_b,16,16,16,__nv_bfloat16,wmma::row_major> bf[2];
                #pragma unroll
                for (int i=0;i<4;i++)
                    wmma::load_matrix_sync(af[i], &As[(size_t)(buf*256+wr*64+i*16)*72 + kk], 72);
                #pragma unroll
                for (int j=0;j<2;j++)
                    wmma::load_matrix_sync(bf[j], &Bs[(size_t)(c*64+kk)*72 + wc*32+j*16], 72);
                #pragma unroll
                for (int i=0;i<4;i++)
                    #pragma unroll
                    for (int j=0;j<2;j++)
                        wmma::mma_sync(acc[i][j], af[i], bf[j], acc[i][j]);
            }
            CP_WAIT0();
            __syncthreads();
        }
    }
    #pragma unroll
    for (int i=0;i<4;i++)
        #pragma unroll
        for (int j=0;j<2;j++)
            wmma::store_matrix_sync(&Cs[(size_t)(wr*64+i*16)*68 + wc*32+j*16], acc[i][j], 68, wmma::mem_row_major);
    __syncthreads();
    return Cs;
}

// qkv: plain bf16 epilogue
__global__ void __launch_bounds__(256,2) k_gemm_qkv(){
    float* Cs = gemm_main<Cdim,C3>(g_win, g_wqkv);
    const int tid = threadIdx.x;
    const int m0 = blockIdx.y*256, n0 = blockIdx.x*64;
    #pragma unroll
    for (int it=0; it<64; it++){
        int idx = it*256+tid;
        int r = idx>>6, cc = idx&63;
        float v = Cs[(size_t)r*68+cc] + g_bqkv[n0+cc];
        g_qkv[(size_t)(m0+r)*C3 + n0 + cc] = __float2bfloat16(v);
    }
}

// fc1: gelu epilogue
__global__ void __launch_bounds__(256,2) k_gemm_fc1(const float* __restrict__ bias){
    float* Cs = gemm_main<Cdim,HID>(g_t, g_wfc1);
    const int tid = threadIdx.x;
    const int m0 = blockIdx.y*256, n0 = blockIdx.x*64;
    #pragma unroll
    for (int it=0; it<64; it++){
        int idx = it*256+tid;
        int r = idx>>6, cc = idx&63;
        float v = Cs[(size_t)r*68+cc] + bias[n0+cc];
        v = 0.5f*v*(1.f+erff(v*0.70710678118654752f));
        g_h[(size_t)(m0+r)*HID + n0 + cc] = __float2bfloat16(v);
    }
}

// proj: fused window-reverse scatter into BCHW yattn + deterministic gap partials
__global__ void __launch_bounds__(256,2) k_gemm_proj_f(const float* __restrict__ bias){
    float* Cs = gemm_main<Cdim,Cdim>(g_attnout, g_wproj);
    __shared__ float sgap[4][64];
    const int tid = threadIdx.x;
    const int m0 = blockIdx.y*256, n0 = blockIdx.x*64;
    const int w0 = m0/64;                 // first of 4 windows (same batch, no straddle)
    const int b  = w0>>10;
    // scatter: token (wi, n) -> pixel b,c,(gh*8+(n>>3))*256 + gw*8+(n&7)
    const int w = (tid>>3)&3, q = tid&7, grp32 = tid>>5;
    {
        int wi = w0 + w;
        int gh = (wi&1023)>>5, gw = wi&31;
        size_t pixbase = (size_t)b*CHW + (size_t)gh*2048 + gw*8 + q;
        #pragma unroll
        for (int it=0; it<64; it++){
            int combo = it*8 + grp32;       // 0..511 = cc*8 + i
            int cc = combo>>3, i = combo&7;
            int r = w*64 + i*8 + q;
            float v = Cs[(size_t)r*68+cc] + bias[n0+cc];
            g_yattn[pixbase + (size_t)(n0+cc)*HW + i*256] = __float2bfloat16(v);
        }
    }
    // gap partials (sum of bf16-rounded outputs per channel over this tile's 256 tokens)
    {
        int cc = tid&63, grp = tid>>6;
        float s = 0.f;
        float bb = bias[n0+cc];
        #pragma unroll
        for (int k=0;k<64;k++){
            int r = grp*64+k;
            s += __bfloat162float(__float2bfloat16(Cs[(size_t)r*68+cc] + bb));
        }
        sgap[grp][cc] = s;
        __syncthreads();
        if (tid < 64){
            float t = sgap[0][tid]+sgap[1][tid]+sgap[2][tid]+sgap[3][tid];
            g_gappart[(size_t)(b*Cdim + n0 + tid)*256 + (blockIdx.y & 255)] = t;
        }
    }
}

// fc2: fused final residual  out = x + yattn*s + fc2(h)
__global__ void __launch_bounds__(256,2) k_gemm_fc2_f(const float* __restrict__ bias,
                                                      const float* __restrict__ x,
                                                      float* __restrict__ out){
    float* Cs = gemm_main<HID,Cdim>(g_h, g_wfc2);
    __shared__ float s_sc[64];
    const int tid = threadIdx.x;
    const int m0 = blockIdx.y*256, n0 = blockIdx.x*64;
    const int b = m0>>16, p0 = m0&65535;
    if (tid < 64) s_sc[tid] = g_s[b*Cdim + n0 + tid];
    __syncthreads();
    #pragma unroll
    for (int it=0; it<64; it++){
        int idx = it*256+tid;
        int cc = idx>>8, pp = idx&255;
        float v = Cs[(size_t)pp*68+cc] + bias[n0+cc];
        size_t off = (size_t)b*CHW + (size_t)(n0+cc)*HW + p0 + pp;
        float y = __bfloat162float(g_yattn[off]);
        out[off] = x[off] + y*s_sc[cc] + v;
    }
}

// ---------------- fused window attention, WMMA: 2 blocks/SM ----------------
#define LDQ 584
#define ATT_SS  74752
#define ATT_CLS 109568
#define ATT_UNI 109824
#define ATT_SM  109832
__global__ void __launch_bounds__(256) k_attn(){
    extern __shared__ __align__(16) char sm[];
    __nv_bfloat16* sQ   = (__nv_bfloat16*)sm;                   // [64][584]
    float*         sS   = (float*)(sm + ATT_SS);                // [8][16*68]  (P aliases this)
    int*           sCls = (int*)(sm + ATT_CLS);                 // [64]
    int*           sUni = (int*)(sm + ATT_UNI);
    int wi = blockIdx.x;
    int tid = threadIdx.x, warp = tid>>5, lane = tid&31;
    int gh = (wi & 1023) >> 5, gw = wi & 31;

    const __nv_bfloat16* qkvb = g_qkv + (size_t)wi*64*C3;
    #pragma unroll
    for (int it=0; it<18; it++){
        int idx = it*256+tid;
        int row = idx/72, u = idx%72;
        *(uint4*)&sQ[row*LDQ + u*8] = *(const uint4*)&qkvb[(size_t)row*C3 + u*8];
    }
    if (tid == 0) sUni[0] = (gh < 31 && gw < 31) ? 1 : 0;
    if (tid < 64){
        int i = tid>>3, j = tid&7;
        int hg = gh*8+i, wg = gw*8+j;
        int rh = hg < 248 ? 0 : (hg < 252 ? 1 : 2);
        int rw = wg < 248 ? 0 : (wg < 252 ? 1 : 2);
        sCls[tid] = rh*3+rw;
    }
    __syncthreads();
    const int uni = sUni[0];

    #pragma unroll
    for (int r=0; r<3; r++){
        int task = warp + 8*r;            // 0..23
        int h = task>>2, strip = task&3, n0 = strip*16;
        float*         Sw = sS + warp*16*68;
        __nv_bfloat16* Pw = (__nv_bfloat16*)Sw;     // alias: reads complete before writes
        // ---- S = Q Kt (16x64) ----
        wmma::fragment<wmma::accumulator,16,16,16,float> acc[4];
        #pragma unroll
        for (int j=0;j<4;j++) wmma::fill_fragment(acc[j], 0.f);
        #pragma unroll
        for (int kk=0; kk<32; kk+=16){
            wmma::fragment<wmma::matrix_a,16,16,16,__nv_bfloat16,wmma::row_major> aq;
            wmma::load_matrix_sync(aq, &sQ[(size_t)n0*LDQ + h*HD + kk], LDQ);
            #pragma unroll
            for (int j=0;j<4;j++){
                wmma::fragment<wmma::matrix_b,16,16,16,__nv_bfloat16,wmma::col_major> bk;
                wmma::load_matrix_sync(bk, &sQ[(size_t)(j*16)*LDQ + Cdim + h*HD + kk], LDQ);
                wmma::mma_sync(acc[j], aq, bk, acc[j]);
            }
        }
        #pragma unroll
        for (int j=0;j<4;j++)
            wmma::store_matrix_sync(&Sw[j*16], acc[j], 68, wmma::mem_row_major);
        __syncwarp();
        // ---- softmax: vector S reads + table bias + uniform-mask fast path ----
        {
            int row = lane>>1, half = (lane&1)*32;
            int n = n0+row;
            const float4* Sv = (const float4*)&Sw[row*68 + half];
            const __nv_bfloat162* bv = (const __nv_bfloat162*)(g_bias + h*4096 + n*64 + half);
            float e[32];
            #pragma unroll
            for (int c4=0;c4<8;c4++){
                float4 s4 = Sv[c4];
                __nv_bfloat162 b0 = bv[c4*2], b1 = bv[c4*2+1];
                e[c4*4+0] = s4.x + __bfloat162float(__low2bfloat16(b0));
                e[c4*4+1] = s4.y + __bfloat162float(__high2bfloat16(b0));
                e[c4*4+2] = s4.z + __bfloat162float(__low2bfloat16(b1));
                e[c4*4+3] = s4.w + __bfloat162float(__high2bfloat16(b1));
            }
            if (!uni){
                int cn = sCls[n];
                #pragma unroll
                for (int c=0;c<32;c++) if (cn != sCls[half+c]) e[c] -= 100.f;
            }
            float mx = -1e30f;
            #pragma unroll
            for (int c=0;c<32;c++) mx = fmaxf(mx, e[c]);
            mx = fmaxf(mx, __shfl_xor_sync(0xffffffffu, mx, 1));   // warp-sync: all reads done
            float sum = 0.f;
            #pragma unroll
            for (int c=0;c<32;c++){ e[c] = __expf(e[c]-mx); sum += e[c]; }
            sum += __shfl_xor_sync(0xffffffffu, sum, 1);
            float inv = 1.f/sum;
            __syncwarp();
            uint32_t* Pv = (uint32_t*)&Pw[row*72 + half];
            #pragma unroll
            for (int c2=0;c2<16;c2++){
                __nv_bfloat162 p2 = __floats2bfloat162_rn(e[c2*2]*inv, e[c2*2+1]*inv);
                Pv[c2] = *(uint32_t*)&p2;
            }
        }
        __syncwarp();
        // ---- out = P V (16x32) ----
        wmma::fragment<wmma::accumulator,16,16,16,float> acc2[2];
        #pragma unroll
        for (int j=0;j<2;j++) wmma::fill_fragment(acc2[j], 0.f);
        #pragma unroll
        for (int k4=0;k4<4;k4++){
            wmma::fragment<wmma::matrix_a,16,16,16,__nv_bfloat16,wmma::row_major> ap;
            wmma::load_matrix_sync(ap, &Pw[k4*16], 72);
            #pragma unroll
            for (int j=0;j<2;j++){
                wmma::fragment<wmma::matrix_b,16,16,16,__nv_bfloat16,wmma::row_major> bv;
                wmma::load_matrix_sync(bv, &sQ[(size_t)(k4*16)*LDQ + 2*Cdim + h*HD + j*16], LDQ);
                wmma::mma_sync(acc2[j], ap, bv, acc2[j]);
            }
        }
        __syncwarp();     // all Pw reads done before overwriting region
        #pragma unroll
        for (int j=0;j<2;j++)
            wmma::store_matrix_sync(&Sw[j*16], acc2[j], 36, wmma::mem_row_major);
        __syncwarp();
        {
            int row = lane>>1, halfo = (lane&1)*16;
            const float4* src = (const float4*)&Sw[row*36 + halfo];
            uint4 o[2];
            #pragma unroll
            for (int q=0;q<2;q++){
                float4 a = src[q*2], b = src[q*2+1];
                __nv_bfloat162 p0 = __floats2bfloat162_rn(a.x, a.y);
                __nv_bfloat162 p1 = __floats2bfloat162_rn(a.z, a.w);
                __nv_bfloat162 p2 = __floats2bfloat162_rn(b.x, b.y);
                __nv_bfloat162 p3 = __floats2bfloat162_rn(b.z, b.w);
                o[q].x = *(uint32_t*)&p0; o[q].y = *(uint32_t*)&p1;
                o[q].z = *(uint32_t*)&p2; o[q].w = *(uint32_t*)&p3;
            }
            uint4* op = (uint4*)(g_attnout + ((size_t)(wi*64 + n0+row))*Cdim + h*HD + halfo);
            op[0] = o[0]; op[1] = o[1];
        }
        __syncwarp();
    }
}

// ---------------- channel attention scale s (deterministic partial-sum reduce) ---------------
__global__ void k_s(const float* __restrict__ caw, const float* __restrict__ cab){
    __shared__ float gg[Bsz*Cdim];
    int tid = threadIdx.x;  // 384
    const float* p = g_gappart + (size_t)tid*256;
    float s = 0.f;
    for (int i=0;i<256;i++) s += p[i];
    gg[tid] = s*(1.f/HW);
    __syncthreads();
    int b = tid/Cdim, o = tid%Cdim;
    float acc = cab[o];
    for (int c=0;c<Cdim;c++) acc += gg[b*Cdim+c]*caw[o*Cdim+c];
    g_s[tid] = acc;
}

// ---------------- x1 = x + yattn*s, norm2, emit BHWC tokens for MLP ----------------
__global__ void k_addnorm2(const float* __restrict__ x,
                           const float* __restrict__ nw, const float* __restrict__ nb){
    __shared__ float tile[Cdim][33];
    __shared__ float red1[8][32], red2[8][32];
    __shared__ float s_mu[32], s_ri[32];
    __shared__ float s_w[Cdim], s_b[Cdim], s_sc[Cdim];
    int b = blockIdx.y;
    int p0 = blockIdx.x*32;
    int tid = threadIdx.x;
    if (tid < Cdim){ s_w[tid]=nw[tid]; s_b[tid]=nb[tid]; s_sc[tid]=g_s[b*Cdim+tid]; }
    __syncthreads();
    const float* xb = x + (size_t)b*CHW;
    const __nv_bfloat16* yb = g_yattn + (size_t)b*CHW;
    #pragma unroll
    for (int it=0; it<24; it++){
        int idx = it*256+tid;
        int c = idx>>5, p = idx&31;
        size_t off = (size_t)c*HW + p0+p;
        tile[c][p] = xb[off] + __bfloat162float(yb[off])*s_sc[c];
    }
    __syncthreads();
    int p = tid&31, g = tid>>5;
    float sum=0.f, sq=0.f;
    for (int c=g; c<Cdim; c+=8){ float v=tile[c][p]; sum+=v; sq+=v*v; }
    red1[g][p]=sum; red2[g][p]=sq;
    __syncthreads();
    if (g==0){
        float s=0.f,q=0.f;
        #pragma unroll
        for (int k=0;k<8;k++){ s+=red1[k][p]; q+=red2[k][p]; }
        float mu = s*(1.f/Cdim);
        float var = q*(1.f/Cdim) - mu*mu;
        s_mu[p]=mu; s_ri[p]=rsqrtf(var+1e-6f);
    }
    __syncthreads();
    #pragma unroll
    for (int it=0; it<24; it++){
        int idx = it*256+tid;
        int pp = idx/192, c = idx%192;
        float v = (tile[c][pp]-s_mu[pp])*s_ri[pp]*s_w[c]+s_b[c];
        g_t[((size_t)b*HW + p0+pp)*Cdim + c] = __float2bfloat16(v);
    }
}

// ---------------- launch ----------------
extern "C" void kernel_launch(void* const* d_in, const int* in_sizes, int n_in,
                              void* d_out, int out_size){
    const float* x    = (const float*)d_in[0];
    const float* n1w  = (const float*)d_in[1];
    const float* n1b  = (const float*)d_in[2];
    const float* qkvw = (const float*)d_in[3];
    const float* qkvb = (const float*)d_in[4];
    const float* projw= (const float*)d_in[5];
    const float* projb= (const float*)d_in[6];
    const float* rpb  = (const float*)d_in[7];
    const float* caw  = (const float*)d_in[8];
    const float* cab  = (const float*)d_in[9];
    const float* n2w  = (const float*)d_in[10];
    const float* n2b  = (const float*)d_in[11];
    const float* fc1w = (const float*)d_in[12];
    const float* fc1b = (const float*)d_in[13];
    const float* fc2w = (const float*)d_in[14];
    const float* fc2b = (const float*)d_in[15];
    float* out = (float*)d_out;

    const int smG = 192*144 + 2*256*144;   // 101376 -> 2 blocks/SM
    static bool attr_done = false;
    if (!attr_done){
        cudaFuncSetAttribute(k_attn,        cudaFuncAttributeMaxDynamicSharedMemorySize, ATT_SM);
        cudaFuncSetAttribute(k_gemm_qkv,    cudaFuncAttributeMaxDynamicSharedMemorySize, smG);
        cudaFuncSetAttribute(k_gemm_proj_f, cudaFuncAttributeMaxDynamicSharedMemorySize, smG);
        cudaFuncSetAttribute(k_gemm_fc1,    cudaFuncAttributeMaxDynamicSharedMemorySize, smG);
        cudaFuncSetAttribute(k_gemm_fc2_f,  cudaFuncAttributeMaxDynamicSharedMemorySize, smG);
        attr_done = true;
    }

    k_conv_all  <<<(Cdim*C3+255)/256, 256>>>(qkvw, qkvb, projw, fc1w, fc2w, rpb);
    k_norm1_roll<<<dim3(HW/32, Bsz), 256>>>(x, n1w, n1b);
    k_win_gather<<<NWIN, 256>>>();
    k_gemm_qkv  <<<dim3(C3/64, NTOK/256),   256, smG>>>();
    k_attn      <<<NWIN, 256, ATT_SM>>>();
    k_gemm_proj_f<<<dim3(Cdim/64, NTOK/256),256, smG>>>(projb);
    k_s         <<<1, 384>>>(caw, cab);
    k_addnorm2  <<<dim3(HW/32, Bsz), 256>>>(x, n2w, n2b);
    k_gemm_fc1  <<<dim3(HID/64, NTOK/256),  256, smG>>>(fc1b);
    k_gemm_fc2_f<<<dim3(Cdim/64, NTOK/256), 256, smG>>>(fc2b, x, out);
}

// round 17
// speedup vs baseline: 1.2728x; 1.0335x over previous
#include <cuda_runtime.h>
#include <cuda_bf16.h>
#include <mma.h>
#include <cstdint>

using namespace nvcuda;

#define Bsz   2
#define Cdim  192
#define Hdim  256
#define Wdim  256
#define HW    65536
#define CHW   12582912
#define NHEAD 6
#define HD    32
#define NTOK  131072
#define C3    576
#define HID   384
#define NWIN  2048

// ---------------- scratch (device globals; no allocation allowed) ----------------
__device__ __nv_bfloat16 g_roll[(size_t)Bsz*CHW];
__device__ __nv_bfloat16 g_win[(size_t)NTOK*Cdim];
__device__ __nv_bfloat16 g_qkv[(size_t)NTOK*C3];
__device__ __nv_bfloat16 g_attnout[(size_t)NTOK*Cdim];
__device__ __nv_bfloat16 g_yattn[(size_t)Bsz*CHW];
__device__ float         g_gappart[(size_t)Bsz*Cdim*256];
__device__ float         g_s[Bsz*Cdim];
__device__ __nv_bfloat16 g_t[(size_t)NTOK*Cdim];
__device__ __nv_bfloat16 g_h[(size_t)NTOK*HID];
__device__ __nv_bfloat16 g_wqkv[Cdim*C3];
__device__ float         g_bqkv[C3];
__device__ __nv_bfloat16 g_wproj[Cdim*Cdim];
__device__ __nv_bfloat16 g_wfc1[Cdim*HID];
__device__ __nv_bfloat16 g_wfc2[HID*Cdim];
__device__ __nv_bfloat16 g_bias[NHEAD*64*64];   // [h][n][m] rpb bias table

// ---------------- helpers ----------------
__device__ __forceinline__ uint32_t smem_u32(const void* p){
    uint32_t a;
    asm("{ .reg .u64 t; cvta.to.shared.u64 t, %1; cvt.u32.u64 %0, t; }" : "=r"(a) : "l"(p));
    return a;
}
__device__ __forceinline__ void cp16(uint32_t dst, const void* src){
    asm volatile("cp.async.cg.shared.global [%0], [%1], 16;" :: "r"(dst), "l"(src));
}
#define CP_COMMIT() asm volatile("cp.async.commit_group;" ::: "memory")
#define CP_WAIT0()  asm volatile("cp.async.wait_group 0;" ::: "memory")

// ---------------- fused: weight conversions + rpb bias table + norm1/roll ----------------
// grid (2048, 3): y<2 -> norm1 for batch y; y==2 -> conversions (x < 432 active)
__global__ void k_prep(const float* __restrict__ x,
                       const float* __restrict__ nw, const float* __restrict__ nb,
                       const float* __restrict__ qw, const float* __restrict__ qb,
                       const float* __restrict__ pw, const float* __restrict__ f1,
                       const float* __restrict__ f2, const float* __restrict__ rpb){
    int tid = threadIdx.x;
    if (blockIdx.y == 2){
        int i = blockIdx.x*256 + tid;
        const float sc = 0.17677669529663687f; // 32^-0.5
        if (i < Cdim*C3){
            int o = i % C3;
            float f = qw[i];
            if (o < Cdim) f *= sc;
            g_wqkv[i] = __float2bfloat16(f);
        }
        if (i < C3){
            float f = qb[i];
            if (i < Cdim) f *= sc;
            g_bqkv[i] = f;
        }
        if (i < Cdim*Cdim) g_wproj[i] = __float2bfloat16(pw[i]);
        if (i < Cdim*HID)  g_wfc1[i]  = __float2bfloat16(f1[i]);
        if (i < HID*Cdim)  g_wfc2[i]  = __float2bfloat16(f2[i]);
        if (i < NHEAD*64*64){
            int h = i >> 12, r = i & 4095;
            int n = r >> 6, m = r & 63;
            int idx = ((n>>3)-(m>>3)+7)*15 + ((n&7)-(m&7)+7);
            g_bias[i] = __float2bfloat16(rpb[idx*NHEAD + h]);
        }
        return;
    }
    __shared__ float tile[Cdim][33];
    __shared__ float red1[8][32], red2[8][32];
    __shared__ float s_mu[32], s_ri[32];
    __shared__ float s_w[Cdim], s_b[Cdim];
    int b = blockIdx.y;
    int p0 = blockIdx.x * 32;
    const float* xb = x + (size_t)b*CHW;
    if (tid < Cdim){ s_w[tid]=nw[tid]; s_b[tid]=nb[tid]; }
    #pragma unroll
    for (int it=0; it<24; it++){
        int idx = it*256+tid;
        int c = idx>>5, p = idx&31;
        tile[c][p] = xb[(size_t)c*HW + p0 + p];
    }
    __syncthreads();
    int p = tid&31, g = tid>>5;
    float sum=0.f, sq=0.f;
    for (int c=g; c<Cdim; c+=8){ float v=tile[c][p]; sum+=v; sq+=v*v; }
    red1[g][p]=sum; red2[g][p]=sq;
    __syncthreads();
    if (g==0){
        float s=0.f,q=0.f;
        #pragma unroll
        for (int k=0;k<8;k++){ s+=red1[k][p]; q+=red2[k][p]; }
        float mu = s*(1.f/Cdim);
        float var = q*(1.f/Cdim) - mu*mu;
        s_mu[p]=mu; s_ri[p]=rsqrtf(var+1e-6f);
    }
    __syncthreads();
    __nv_bfloat16* rb = g_roll + (size_t)b*CHW;
    #pragma unroll
    for (int it=0; it<24; it++){
        int idx = it*256+tid;
        int c = idx>>5, pp = idx&31;
        float v = (tile[c][pp]-s_mu[pp])*s_ri[pp]*s_w[c]+s_b[c];
        int f = c*HW + p0 + pp;
        int i = f/49152; int r = f - i*49152; int j = r/192; int k = r - j*192;
        int t = ((i-4)&255)*49152 + ((j-4)&255)*192 + k;
        rb[t] = __float2bfloat16(v);
    }
}

// ---------------- window partition: rolled BCHW -> (win, n, c) tokens ----------------
__global__ void k_win_gather(){
    __shared__ __nv_bfloat16 s[96][66];
    int wi = blockIdx.x; int tid = threadIdx.x;
    int b = wi>>10, gh=(wi&1023)>>5, gw=wi&31;
    const __nv_bfloat16* rb = g_roll + (size_t)b*CHW;
    size_t base = (size_t)(gh*8)*256 + gw*8;
    for (int chunk=0; chunk<2; chunk++){
        int c0 = chunk*96;
        #pragma unroll
        for (int it=0; it<24; it++){
            int idx = it*256+tid;
            int cl = idx>>6, n = idx&63;
            s[cl][n] = rb[(size_t)(c0+cl)*HW + base + (n>>3)*256 + (n&7)];
        }
        __syncthreads();
        #pragma unroll
        for (int it=0; it<24; it++){
            int idx = it*256+tid;
            int n = idx/96, cl = idx%96;
            g_win[((size_t)wi*64+n)*Cdim + c0 + cl] = s[cl][n];
        }
        __syncthreads();
    }
}

// ---------------- GEMM mainloop: 256x64 CTA tile, 8 warps x (64x32), ldm=72, cp.async --------
// Grid: (N/64, NTOK/256) — N-tiles fastest so co-resident blocks share A rows (L2 reuse).
template<int K, int N>
__device__ __forceinline__ float* gemm_main(const __nv_bfloat16* __restrict__ A,
                                            const __nv_bfloat16* __restrict__ Bm){
    extern __shared__ __align__(16) char sm[];
    __nv_bfloat16* Bs = (__nv_bfloat16*)sm;                       // [192][72]
    __nv_bfloat16* As = (__nv_bfloat16*)(sm + 192*144);           // [2][256][72]
    float*         Cs = (float*)(sm + 192*144);                   // [256][68] (aliases As)
    const uint32_t sB = smem_u32(sm);
    const uint32_t sA = sB + 192*144;
    const int tid = threadIdx.x;
    const int m0 = blockIdx.y*256, n0 = blockIdx.x*64;
    const int warp = tid>>5, wr = warp>>1, wc = warp&1;

    auto loadB = [&](int s){
        #pragma unroll
        for (int it=0; it<6; it++){
            int idx = it*256+tid;
            int row = idx>>3, u = idx&7;
            cp16(sB + row*144 + u*16, &Bm[(size_t)(s*192+row)*N + n0 + u*8]);
        }
    };
    auto loadA = [&](int s, int c, int buf){
        #pragma unroll
        for (int it=0; it<8; it++){
            int idx = it*256+tid;
            int row = idx>>3, u = idx&7;
            cp16(sA + (buf*256+row)*144 + u*16,
                 &A[(size_t)(m0+row)*K + s*192 + c*64 + u*8]);
        }
    };

    wmma::fragment<wmma::accumulator,16,16,16,float> acc[4][2];
    #pragma unroll
    for (int i=0;i<4;i++)
        #pragma unroll
        for (int j=0;j<2;j++) wmma::fill_fragment(acc[i][j], 0.f);

    constexpr int NS = K/192;
    #pragma unroll
    for (int s=0;s<NS;s++){
        loadB(s);
        loadA(s,0,0);
        CP_COMMIT(); CP_WAIT0();
        __syncthreads();
        #pragma unroll
        for (int c=0;c<3;c++){
            if (c<2){ loadA(s,c+1,(c+1)&1); CP_COMMIT(); }
            int buf = c&1;
            #pragma unroll
            for (int kk=0;kk<64;kk+=16){
                wmma::fragment<wmma::matrix_a,16,16,16,__nv_bfloat16,wmma::row_major> af[4];
                wmma::fragment<wmma::matrix_b,16,16,16,__nv_bfloat16,wmma::row_major> bf[2];
                #pragma unroll
                for (int i=0;i<4;i++)
                    wmma::load_matrix_sync(af[i], &As[(size_t)(buf*256+wr*64+i*16)*72 + kk], 72);
                #pragma unroll
                for (int j=0;j<2;j++)
                    wmma::load_matrix_sync(bf[j], &Bs[(size_t)(c*64+kk)*72 + wc*32+j*16], 72);
                #pragma unroll
                for (int i=0;i<4;i++)
                    #pragma unroll
                    for (int j=0;j<2;j++)
                        wmma::mma_sync(acc[i][j], af[i], bf[j], acc[i][j]);
            }
            CP_WAIT0();
            __syncthreads();
        }
    }
    #pragma unroll
    for (int i=0;i<4;i++)
        #pragma unroll
        for (int j=0;j<2;j++)
            wmma::store_matrix_sync(&Cs[(size_t)(wr*64+i*16)*68 + wc*32+j*16], acc[i][j], 68, wmma::mem_row_major);
    __syncthreads();
    return Cs;
}

// qkv: plain bf16 epilogue
__global__ void __launch_bounds__(256,2) k_gemm_qkv(){
    float* Cs = gemm_main<Cdim,C3>(g_win, g_wqkv);
    const int tid = threadIdx.x;
    const int m0 = blockIdx.y*256, n0 = blockIdx.x*64;
    #pragma unroll
    for (int it=0; it<64; it++){
        int idx = it*256+tid;
        int r = idx>>6, cc = idx&63;
        float v = Cs[(size_t)r*68+cc] + g_bqkv[n0+cc];
        g_qkv[(size_t)(m0+r)*C3 + n0 + cc] = __float2bfloat16(v);
    }
}

// fc1: gelu epilogue
__global__ void __launch_bounds__(256,2) k_gemm_fc1(const float* __restrict__ bias){
    float* Cs = gemm_main<Cdim,HID>(g_t, g_wfc1);
    const int tid = threadIdx.x;
    const int m0 = blockIdx.y*256, n0 = blockIdx.x*64;
    #pragma unroll
    for (int it=0; it<64; it++){
        int idx = it*256+tid;
        int r = idx>>6, cc = idx&63;
        float v = Cs[(size_t)r*68+cc] + bias[n0+cc];
        v = 0.5f*v*(1.f+erff(v*0.70710678118654752f));
        g_h[(size_t)(m0+r)*HID + n0 + cc] = __float2bfloat16(v);
    }
}

// proj: fused window-reverse scatter into BCHW yattn + deterministic gap partials
__global__ void __launch_bounds__(256,2) k_gemm_proj_f(const float* __restrict__ bias){
    float* Cs = gemm_main<Cdim,Cdim>(g_attnout, g_wproj);
    __shared__ float sgap[4][64];
    const int tid = threadIdx.x;
    const int m0 = blockIdx.y*256, n0 = blockIdx.x*64;
    const int w0 = m0/64;                 // first of 4 windows (same batch, no straddle)
    const int b  = w0>>10;
    // scatter: token (wi, n) -> pixel b,c,(gh*8+(n>>3))*256 + gw*8+(n&7)
    const int w = (tid>>3)&3, q = tid&7, grp32 = tid>>5;
    {
        int wi = w0 + w;
        int gh = (wi&1023)>>5, gw = wi&31;
        size_t pixbase = (size_t)b*CHW + (size_t)gh*2048 + gw*8 + q;
        #pragma unroll
        for (int it=0; it<64; it++){
            int combo = it*8 + grp32;       // 0..511 = cc*8 + i
            int cc = combo>>3, i = combo&7;
            int r = w*64 + i*8 + q;
            float v = Cs[(size_t)r*68+cc] + bias[n0+cc];
            g_yattn[pixbase + (size_t)(n0+cc)*HW + i*256] = __float2bfloat16(v);
        }
    }
    // gap partials (sum of bf16-rounded outputs per channel over this tile's 256 tokens)
    {
        int cc = tid&63, grp = tid>>6;
        float s = 0.f;
        float bb = bias[n0+cc];
        #pragma unroll
        for (int k=0;k<64;k++){
            int r = grp*64+k;
            s += __bfloat162float(__float2bfloat16(Cs[(size_t)r*68+cc] + bb));
        }
        sgap[grp][cc] = s;
        __syncthreads();
        if (tid < 64){
            float t = sgap[0][tid]+sgap[1][tid]+sgap[2][tid]+sgap[3][tid];
            g_gappart[(size_t)(b*Cdim + n0 + tid)*256 + (blockIdx.y & 255)] = t;
        }
    }
}

// fc2: fused final residual  out = x + yattn*s + fc2(h)
__global__ void __launch_bounds__(256,2) k_gemm_fc2_f(const float* __restrict__ bias,
                                                      const float* __restrict__ x,
                                                      float* __restrict__ out){
    float* Cs = gemm_main<HID,Cdim>(g_h, g_wfc2);
    __shared__ float s_sc[64];
    const int tid = threadIdx.x;
    const int m0 = blockIdx.y*256, n0 = blockIdx.x*64;
    const int b = m0>>16, p0 = m0&65535;
    if (tid < 64) s_sc[tid] = g_s[b*Cdim + n0 + tid];
    __syncthreads();
    #pragma unroll
    for (int it=0; it<64; it++){
        int idx = it*256+tid;
        int cc = idx>>8, pp = idx&255;
        float v = Cs[(size_t)pp*68+cc] + bias[n0+cc];
        size_t off = (size_t)b*CHW + (size_t)(n0+cc)*HW + p0 + pp;
        float y = __bfloat162float(g_yattn[off]);
        out[off] = x[off] + y*s_sc[cc] + v;
    }
}

// ---------------- fused window attention, WMMA: 2 blocks/SM ----------------
#define LDQ 584
#define ATT_SS  74752
#define ATT_CLS 109568
#define ATT_UNI 109824
#define ATT_SM  109832
__global__ void __launch_bounds__(256) k_attn(){
    extern __shared__ __align__(16) char sm[];
    __nv_bfloat16* sQ   = (__nv_bfloat16*)sm;                   // [64][584]
    float*         sS   = (float*)(sm + ATT_SS);                // [8][16*68]  (P aliases this)
    int*           sCls = (int*)(sm + ATT_CLS);                 // [64]
    int*           sUni = (int*)(sm + ATT_UNI);
    int wi = blockIdx.x;
    int tid = threadIdx.x, warp = tid>>5, lane = tid&31;
    int gh = (wi & 1023) >> 5, gw = wi & 31;

    const __nv_bfloat16* qkvb = g_qkv + (size_t)wi*64*C3;
    #pragma unroll
    for (int it=0; it<18; it++){
        int idx = it*256+tid;
        int row = idx/72, u = idx%72;
        *(uint4*)&sQ[row*LDQ + u*8] = *(const uint4*)&qkvb[(size_t)row*C3 + u*8];
    }
    if (tid == 0) sUni[0] = (gh < 31 && gw < 31) ? 1 : 0;
    if (tid < 64){
        int i = tid>>3, j = tid&7;
        int hg = gh*8+i, wg = gw*8+j;
        int rh = hg < 248 ? 0 : (hg < 252 ? 1 : 2);
        int rw = wg < 248 ? 0 : (wg < 252 ? 1 : 2);
        sCls[tid] = rh*3+rw;
    }
    __syncthreads();
    const int uni = sUni[0];

    #pragma unroll
    for (int r=0; r<3; r++){
        int task = warp + 8*r;            // 0..23
        int h = task>>2, strip = task&3, n0 = strip*16;
        float*         Sw = sS + warp*16*68;
        __nv_bfloat16* Pw = (__nv_bfloat16*)Sw;     // alias: reads complete before writes
        // ---- S = Q Kt (16x64) ----
        wmma::fragment<wmma::accumulator,16,16,16,float> acc[4];
        #pragma unroll
        for (int j=0;j<4;j++) wmma::fill_fragment(acc[j], 0.f);
        #pragma unroll
        for (int kk=0; kk<32; kk+=16){
            wmma::fragment<wmma::matrix_a,16,16,16,__nv_bfloat16,wmma::row_major> aq;
            wmma::load_matrix_sync(aq, &sQ[(size_t)n0*LDQ + h*HD + kk], LDQ);
            #pragma unroll
            for (int j=0;j<4;j++){
                wmma::fragment<wmma::matrix_b,16,16,16,__nv_bfloat16,wmma::col_major> bk;
                wmma::load_matrix_sync(bk, &sQ[(size_t)(j*16)*LDQ + Cdim + h*HD + kk], LDQ);
                wmma::mma_sync(acc[j], aq, bk, acc[j]);
            }
        }
        #pragma unroll
        for (int j=0;j<4;j++)
            wmma::store_matrix_sync(&Sw[j*16], acc[j], 68, wmma::mem_row_major);
        __syncwarp();
        // ---- softmax: vector S reads + table bias + uniform-mask fast path ----
        {
            int row = lane>>1, half = (lane&1)*32;
            int n = n0+row;
            const float4* Sv = (const float4*)&Sw[row*68 + half];
            const __nv_bfloat162* bv = (const __nv_bfloat162*)(g_bias + h*4096 + n*64 + half);
            float e[32];
            #pragma unroll
            for (int c4=0;c4<8;c4++){
                float4 s4 = Sv[c4];
                __nv_bfloat162 b0 = bv[c4*2], b1 = bv[c4*2+1];
                e[c4*4+0] = s4.x + __bfloat162float(__low2bfloat16(b0));
                e[c4*4+1] = s4.y + __bfloat162float(__high2bfloat16(b0));
                e[c4*4+2] = s4.z + __bfloat162float(__low2bfloat16(b1));
                e[c4*4+3] = s4.w + __bfloat162float(__high2bfloat16(b1));
            }
            if (!uni){
                int cn = sCls[n];
                #pragma unroll
                for (int c=0;c<32;c++) if (cn != sCls[half+c]) e[c] -= 100.f;
            }
            float mx = -1e30f;
            #pragma unroll
            for (int c=0;c<32;c++) mx = fmaxf(mx, e[c]);
            mx = fmaxf(mx, __shfl_xor_sync(0xffffffffu, mx, 1));   // warp-sync: all reads done
            float sum = 0.f;
            #pragma unroll
            for (int c=0;c<32;c++){ e[c] = __expf(e[c]-mx); sum += e[c]; }
            sum += __shfl_xor_sync(0xffffffffu, sum, 1);
            float inv = 1.f/sum;
            __syncwarp();
            uint32_t* Pv = (uint32_t*)&Pw[row*72 + half];
            #pragma unroll
            for (int c2=0;c2<16;c2++){
                __nv_bfloat162 p2 = __floats2bfloat162_rn(e[c2*2]*inv, e[c2*2+1]*inv);
                Pv[c2] = *(uint32_t*)&p2;
            }
        }
        __syncwarp();
        // ---- out = P V (16x32) ----
        wmma::fragment<wmma::accumulator,16,16,16,float> acc2[2];
        #pragma unroll
        for (int j=0;j<2;j++) wmma::fill_fragment(acc2[j], 0.f);
        #pragma unroll
        for (int k4=0;k4<4;k4++){
            wmma::fragment<wmma::matrix_a,16,16,16,__nv_bfloat16,wmma::row_major> ap;
            wmma::load_matrix_sync(ap, &Pw[k4*16], 72);
            #pragma unroll
            for (int j=0;j<2;j++){
                wmma::fragment<wmma::matrix_b,16,16,16,__nv_bfloat16,wmma::row_major> bv;
                wmma::load_matrix_sync(bv, &sQ[(size_t)(k4*16)*LDQ + 2*Cdim + h*HD + j*16], LDQ);
                wmma::mma_sync(acc2[j], ap, bv, acc2[j]);
            }
        }
        __syncwarp();     // all Pw reads done before overwriting region
        #pragma unroll
        for (int j=0;j<2;j++)
            wmma::store_matrix_sync(&Sw[j*16], acc2[j], 36, wmma::mem_row_major);
        __syncwarp();
        {
            int row = lane>>1, halfo = (lane&1)*16;
            const float4* src = (const float4*)&Sw[row*36 + halfo];
            uint4 o[2];
            #pragma unroll
            for (int q=0;q<2;q++){
                float4 a = src[q*2], b = src[q*2+1];
                __nv_bfloat162 p0 = __floats2bfloat162_rn(a.x, a.y);
                __nv_bfloat162 p1 = __floats2bfloat162_rn(a.z, a.w);
                __nv_bfloat162 p2 = __floats2bfloat162_rn(b.x, b.y);
                __nv_bfloat162 p3 = __floats2bfloat162_rn(b.z, b.w);
                o[q].x = *(uint32_t*)&p0; o[q].y = *(uint32_t*)&p1;
                o[q].z = *(uint32_t*)&p2; o[q].w = *(uint32_t*)&p3;
            }
            uint4* op = (uint4*)(g_attnout + ((size_t)(wi*64 + n0+row))*Cdim + h*HD + halfo);
            op[0] = o[0]; op[1] = o[1];
        }
        __syncwarp();
    }
}

// ---------------- channel attention scale s (deterministic partial-sum reduce) ---------------
__global__ void k_s(const float* __restrict__ caw, const float* __restrict__ cab){
    __shared__ float gg[Bsz*Cdim];
    int tid = threadIdx.x;  // 384
    const float* p = g_gappart + (size_t)tid*256;
    float s = 0.f;
    for (int i=0;i<256;i++) s += p[i];
    gg[tid] = s*(1.f/HW);
    __syncthreads();
    int b = tid/Cdim, o = tid%Cdim;
    float acc = cab[o];
    for (int c=0;c<Cdim;c++) acc += gg[b*Cdim+c]*caw[o*Cdim+c];
    g_s[tid] = acc;
}

// ---------------- x1 = x + yattn*s, norm2, emit BHWC tokens for MLP ----------------
__global__ void k_addnorm2(const float* __restrict__ x,
                           const float* __restrict__ nw, const float* __restrict__ nb){
    __shared__ float tile[Cdim][33];
    __shared__ float red1[8][32], red2[8][32];
    __shared__ float s_mu[32], s_ri[32];
    __shared__ float s_w[Cdim], s_b[Cdim], s_sc[Cdim];
    int b = blockIdx.y;
    int p0 = blockIdx.x*32;
    int tid = threadIdx.x;
    if (tid < Cdim){ s_w[tid]=nw[tid]; s_b[tid]=nb[tid]; s_sc[tid]=g_s[b*Cdim+tid]; }
    __syncthreads();
    const float* xb = x + (size_t)b*CHW;
    const __nv_bfloat16* yb = g_yattn + (size_t)b*CHW;
    #pragma unroll
    for (int it=0; it<24; it++){
        int idx = it*256+tid;
        int c = idx>>5, p = idx&31;
        size_t off = (size_t)c*HW + p0+p;
        tile[c][p] = xb[off] + __bfloat162float(yb[off])*s_sc[c];
    }
    __syncthreads();
    int p = tid&31, g = tid>>5;
    float sum=0.f, sq=0.f;
    for (int c=g; c<Cdim; c+=8){ float v=tile[c][p]; sum+=v; sq+=v*v; }
    red1[g][p]=sum; red2[g][p]=sq;
    __syncthreads();
    if (g==0){
        float s=0.f,q=0.f;
        #pragma unroll
        for (int k=0;k<8;k++){ s+=red1[k][p]; q+=red2[k][p]; }
        float mu = s*(1.f/Cdim);
        float var = q*(1.f/Cdim) - mu*mu;
        s_mu[p]=mu; s_ri[p]=rsqrtf(var+1e-6f);
    }
    __syncthreads();
    #pragma unroll
    for (int it=0; it<24; it++){
        int idx = it*256+tid;
        int pp = idx/192, c = idx%192;
        float v = (tile[c][pp]-s_mu[pp])*s_ri[pp]*s_w[c]+s_b[c];
        g_t[((size_t)b*HW + p0+pp)*Cdim + c] = __float2bfloat16(v);
    }
}

// ---------------- launch ----------------
extern "C" void kernel_launch(void* const* d_in, const int* in_sizes, int n_in,
                              void* d_out, int out_size){
    const float* x    = (const float*)d_in[0];
    const float* n1w  = (const float*)d_in[1];
    const float* n1b  = (const float*)d_in[2];
    const float* qkvw = (const float*)d_in[3];
    const float* qkvb = (const float*)d_in[4];
    const float* projw= (const float*)d_in[5];
    const float* projb= (const float*)d_in[6];
    const float* rpb  = (const float*)d_in[7];
    const float* caw  = (const float*)d_in[8];
    const float* cab  = (const float*)d_in[9];
    const float* n2w  = (const float*)d_in[10];
    const float* n2b  = (const float*)d_in[11];
    const float* fc1w = (const float*)d_in[12];
    const float* fc1b = (const float*)d_in[13];
    const float* fc2w = (const float*)d_in[14];
    const float* fc2b = (const float*)d_in[15];
    float* out = (float*)d_out;

    const int smG = 192*144 + 2*256*144;   // 101376 -> 2 blocks/SM
    static bool attr_done = false;
    if (!attr_done){
        cudaFuncSetAttribute(k_attn,        cudaFuncAttributeMaxDynamicSharedMemorySize, ATT_SM);
        cudaFuncSetAttribute(k_gemm_qkv,    cudaFuncAttributeMaxDynamicSharedMemorySize, smG);
        cudaFuncSetAttribute(k_gemm_proj_f, cudaFuncAttributeMaxDynamicSharedMemorySize, smG);
        cudaFuncSetAttribute(k_gemm_fc1,    cudaFuncAttributeMaxDynamicSharedMemorySize, smG);
        cudaFuncSetAttribute(k_gemm_fc2_f,  cudaFuncAttributeMaxDynamicSharedMemorySize, smG);
        attr_done = true;
    }

    k_prep      <<<dim3(HW/32, 3), 256>>>(x, n1w, n1b, qkvw, qkvb, projw, fc1w, fc2w, rpb);
    k_win_gather<<<NWIN, 256>>>();
    k_gemm_qkv  <<<dim3(C3/64, NTOK/256),   256, smG>>>();
    k_attn      <<<NWIN, 256, ATT_SM>>>();
    k_gemm_proj_f<<<dim3(Cdim/64, NTOK/256),256, smG>>>(projb);
    k_s         <<<1, 384>>>(caw, cab);
    k_addnorm2  <<<dim3(HW/32, Bsz), 256>>>(x, n2w, n2b);
    k_gemm_fc1  <<<dim3(HID/64, NTOK/256),  256, smG>>>(fc1b);
    k_gemm_fc2_f<<<dim3(Cdim/64, NTOK/256), 256, smG>>>(fc2b, x, out);
}